// round 1
// baseline (speedup 1.0000x reference)
#include <cuda_runtime.h>
#include <cstdint>
#include <cstddef>

// ---------------- problem constants ----------------
#define NB      32
#define T_STEP  16
#define NPATCH  49
#define SEQL    784            // T_STEP * NPATCH
#define TOK     25088          // NB * SEQL
#define DIM     512
#define HEADS   8
#define DH      64
#define MLPD    2048
#define PDIM    432
#define DEPTH   4

// ---------------- scratch (device globals; no allocations allowed) ----------------
__device__ float g_x  [(size_t)TOK * DIM];
__device__ float g_h  [(size_t)TOK * DIM];
__device__ float g_qkv[(size_t)TOK * 3 * DIM];
__device__ float g_att[(size_t)TOK * DIM];
__device__ float g_mlp[(size_t)TOK * MLPD];
__device__ float g_keep[(size_t)NB * SEQL];

// ---------------- epilogue modes ----------------
#define EPI_NONE  0
#define EPI_EMBED 1
#define EPI_RES   2
#define EPI_GELU  3

// ---------------- mask kernel ----------------
__global__ void keep_kernel(const int* __restrict__ done, float* __restrict__ keep)
{
    int n = threadIdx.x;
    if (n >= NB) return;
    float kv[T_STEP];
    int flag = 0;
    for (int t = T_STEP - 2; t >= 0; --t) {
        flag |= done[n * (T_STEP - 1) + t];
        kv[t] = flag ? 0.f : 1.f;
    }
    kv[T_STEP - 1] = 1.f;
    for (int t = 0; t < T_STEP; ++t) {
        float v = kv[t];
        for (int p = 0; p < NPATCH; ++p)
            keep[(size_t)n * SEQL + t * NPATCH + p] = v;
    }
}

// ---------------- generic SGEMM: C = A[MxK] @ B[KxN] + bias, fused epilogue ----------
// 128x128 tile, BK=8, 256 threads, 8x8 per thread. Requires M%128==0, N%128==0, K%8==0.
__global__ __launch_bounds__(256, 2)
void sgemm_kernel(const float* __restrict__ A, const float* __restrict__ B,
                  const float* __restrict__ bias, const float* __restrict__ res,
                  float* __restrict__ C, int M, int N, int K, int epi,
                  const float* __restrict__ sp, const float* __restrict__ tp)
{
    __shared__ float As[8][128];
    __shared__ float Bs[8][128];

    const int tid = threadIdx.x;
    const int bx = blockIdx.x;   // N tile
    const int by = blockIdx.y;   // M tile

    const int aRow = tid >> 1;            // 0..127
    const int aCol = (tid & 1) * 4;       // 0 or 4
    const int bRow = tid >> 5;            // 0..7
    const int bCol = (tid & 31) * 4;      // 0..124

    const int tx = tid & 15;
    const int ty = tid >> 4;

    float acc[8][8];
#pragma unroll
    for (int i = 0; i < 8; ++i)
#pragma unroll
        for (int j = 0; j < 8; ++j) acc[i][j] = 0.f;

    const float* Aptr = A + (size_t)(by * 128 + aRow) * K + aCol;
    const float* Bptr = B + (size_t)bRow * N + bx * 128 + bCol;

    for (int k0 = 0; k0 < K; k0 += 8) {
        float4 a4 = *(const float4*)(Aptr + k0);
        As[aCol + 0][aRow] = a4.x;
        As[aCol + 1][aRow] = a4.y;
        As[aCol + 2][aRow] = a4.z;
        As[aCol + 3][aRow] = a4.w;
        float4 b4 = *(const float4*)(Bptr + (size_t)k0 * N);
        *(float4*)&Bs[bRow][bCol] = b4;
        __syncthreads();

#pragma unroll
        for (int k = 0; k < 8; ++k) {
            float ar[8], br[8];
#pragma unroll
            for (int i = 0; i < 8; ++i) ar[i] = As[k][ty * 8 + i];
#pragma unroll
            for (int j = 0; j < 8; ++j) br[j] = Bs[k][tx * 8 + j];
#pragma unroll
            for (int i = 0; i < 8; ++i)
#pragma unroll
                for (int j = 0; j < 8; ++j)
                    acc[i][j] = fmaf(ar[i], br[j], acc[i][j]);
        }
        __syncthreads();
    }

    const int col0 = bx * 128 + tx * 8;
#pragma unroll
    for (int i = 0; i < 8; ++i) {
        const int r = by * 128 + ty * 8 + i;
        float* crow = C + (size_t)r * N + col0;
        const int l = r % SEQL;
        const int tt = l / NPATCH;
        const int pp = l % NPATCH;
#pragma unroll
        for (int j = 0; j < 8; ++j) {
            const int col = col0 + j;
            float v = acc[i][j] + bias[col];
            if (epi == EPI_EMBED) {
                v += sp[(size_t)pp * DIM + col] + tp[(size_t)tt * DIM + col];
            } else if (epi == EPI_RES) {
                v += res[(size_t)r * N + col];
            } else if (epi == EPI_GELU) {
                v = 0.5f * v * (1.0f + erff(v * 0.70710678118654752f));
            }
            crow[j] = v;
        }
    }
}

// ---------------- LayerNorm: one block (128 thr) per row of 512 ----------------
__global__ void ln_kernel(const float* __restrict__ x, const float* __restrict__ g,
                          const float* __restrict__ b, float* __restrict__ y)
{
    const int row = blockIdx.x;
    const int tid = threadIdx.x;   // 128
    const float4 v = *(const float4*)(x + (size_t)row * DIM + tid * 4);

    __shared__ float red[4];
    float s = v.x + v.y + v.z + v.w;
#pragma unroll
    for (int o = 16; o > 0; o >>= 1) s += __shfl_xor_sync(0xffffffffu, s, o);
    if ((tid & 31) == 0) red[tid >> 5] = s;
    __syncthreads();
    const float mean = (red[0] + red[1] + red[2] + red[3]) * (1.0f / DIM);

    const float d0 = v.x - mean, d1 = v.y - mean, d2 = v.z - mean, d3 = v.w - mean;
    float q = d0 * d0 + d1 * d1 + d2 * d2 + d3 * d3;
    __syncthreads();
#pragma unroll
    for (int o = 16; o > 0; o >>= 1) q += __shfl_xor_sync(0xffffffffu, q, o);
    if ((tid & 31) == 0) red[tid >> 5] = q;
    __syncthreads();
    const float var = (red[0] + red[1] + red[2] + red[3]) * (1.0f / DIM);
    const float rs = rsqrtf(var + 1e-5f);

    const float4 gv = *(const float4*)(g + tid * 4);
    const float4 bv = *(const float4*)(b + tid * 4);
    float4 o4;
    o4.x = d0 * rs * gv.x + bv.x;
    o4.y = d1 * rs * gv.y + bv.y;
    o4.z = d2 * rs * gv.z + bv.z;
    o4.w = d3 * rs * gv.w + bv.w;
    *(float4*)(y + (size_t)row * DIM + tid * 4) = o4;
}

// ---------------- flash-style attention ----------------
// grid (13, HEADS, NB), 256 threads. 64-query CTA tile, 64-key KV tiles.
// Mask semantics (matching the fp32 reference with -1e9 bias):
//   keep_q == 1: attend only to keys with keep_k == 1 (others weight exactly 0)
//   keep_q == 0: -1e9 is added to EVERY score, which in fp32 collapses all scores to
//                exactly -1e9 -> softmax is exactly UNIFORM over all 784 keys.
#define AT   64
#define APAD 68
__global__ __launch_bounds__(256)
void attn_kernel(const float* __restrict__ qkv, const float* __restrict__ keep,
                 float* __restrict__ out)
{
    extern __shared__ float sm[];
    float* Qt   = sm;                    // [64][APAD]  d-major (Qt[d][q])
    float* Kt   = Qt + AT * APAD;        // [64][APAD]  d-major (Kt[d][k])
    float* Vs   = Kt + AT * APAD;        // [64][APAD]  token-major (Vs[k][d])
    float* Ps   = Vs + AT * APAD;        // [64][APAD]
    float* mrow = Ps + AT * APAD;        // [64]
    float* lrow = mrow + AT;
    float* crow = lrow + AT;
    float* kqs  = crow + AT;             // keep_q per row
    float* kks  = kqs + AT;              // keep_k per col

    const int qt = blockIdx.x;
    const int h  = blockIdx.y;
    const int n  = blockIdx.z;
    const int tid = threadIdx.x;
    const int tx = tid & 15;
    const int ty = tid >> 4;
    const int tx4 = tx * 4, ty4 = ty * 4;
    const int q0 = qt * AT;

    const float* base = qkv + (size_t)n * SEQL * (3 * DIM);

    // load Q tile (transposed into Qt[d][q])
#pragma unroll
    for (int it = 0; it < 4; ++it) {
        int idx = tid + it * 256;
        int row = idx >> 4;
        int cg  = (idx & 15) * 4;
        int qrow = q0 + row;
        int src = qrow < SEQL ? qrow : (SEQL - 1);
        float4 v = *(const float4*)(base + (size_t)src * (3 * DIM) + h * DH + cg);
        Qt[(cg + 0) * APAD + row] = v.x;
        Qt[(cg + 1) * APAD + row] = v.y;
        Qt[(cg + 2) * APAD + row] = v.z;
        Qt[(cg + 3) * APAD + row] = v.w;
    }
    if (tid < AT) {
        int qrow = q0 + tid;
        kqs[tid] = (qrow < SEQL) ? keep[(size_t)n * SEQL + qrow] : 0.f;
        mrow[tid] = -1e30f;
        lrow[tid] = 0.f;
    }
    float o[4][4];
#pragma unroll
    for (int i = 0; i < 4; ++i)
#pragma unroll
        for (int j = 0; j < 4; ++j) o[i][j] = 0.f;
    __syncthreads();

    float kqv[4];
#pragma unroll
    for (int i = 0; i < 4; ++i) kqv[i] = kqs[ty4 + i];

    for (int kt0 = 0; kt0 < SEQL; kt0 += AT) {
        // load K (transposed) and V (natural)
#pragma unroll
        for (int it = 0; it < 4; ++it) {
            int idx = tid + it * 256;
            int row = idx >> 4;
            int cg  = (idx & 15) * 4;
            int krow = kt0 + row;
            int src = krow < SEQL ? krow : (SEQL - 1);
            const float* kp = base + (size_t)src * (3 * DIM) + DIM + h * DH + cg;
            float4 k4 = *(const float4*)kp;
            Kt[(cg + 0) * APAD + row] = k4.x;
            Kt[(cg + 1) * APAD + row] = k4.y;
            Kt[(cg + 2) * APAD + row] = k4.z;
            Kt[(cg + 3) * APAD + row] = k4.w;
            const float* vp = base + (size_t)src * (3 * DIM) + 2 * DIM + h * DH + cg;
            float4 v4 = *(const float4*)vp;
            *(float4*)&Vs[row * APAD + cg] = v4;
        }
        if (tid < AT)
            kks[tid] = (kt0 + tid < SEQL) ? keep[(size_t)n * SEQL + kt0 + tid] : 0.f;
        __syncthreads();

        // S = Q @ K^T (4x4 per thread)
        float s[4][4];
#pragma unroll
        for (int i = 0; i < 4; ++i)
#pragma unroll
            for (int j = 0; j < 4; ++j) s[i][j] = 0.f;
#pragma unroll 8
        for (int d = 0; d < DH; ++d) {
            float a[4], bb[4];
#pragma unroll
            for (int i = 0; i < 4; ++i) a[i] = Qt[d * APAD + ty4 + i];
#pragma unroll
            for (int j = 0; j < 4; ++j) bb[j] = Kt[d * APAD + tx4 + j];
#pragma unroll
            for (int i = 0; i < 4; ++i)
#pragma unroll
                for (int j = 0; j < 4; ++j)
                    s[i][j] = fmaf(a[i], bb[j], s[i][j]);
        }

        // mask/scale and write P
#pragma unroll
        for (int i = 0; i < 4; ++i) {
#pragma unroll
            for (int j = 0; j < 4; ++j) {
                int kidx = kt0 + tx4 + j;
                float val;
                if (kidx >= SEQL) {
                    val = -1e30f;
                } else if (kqv[i] > 0.5f) {
                    val = (kks[tx4 + j] > 0.5f) ? s[i][j] * 0.125f : -1e30f;
                } else {
                    val = 0.f;   // fully-masked row -> uniform softmax
                }
                Ps[(ty4 + i) * APAD + tx4 + j] = val;
            }
        }
        __syncthreads();

        // online softmax per row (rows handled by threads 0..63)
        if (tid < AT) {
            float* pr = Ps + tid * APAD;
            float mo = mrow[tid];
            float tm = -1e30f;
#pragma unroll 8
            for (int k = 0; k < AT; ++k) tm = fmaxf(tm, pr[k]);
            float mn = fmaxf(mo, tm);
            float c = __expf(mo - mn);     // mo==mn==-1e30 -> 1, O is 0 anyway
            float srow = 0.f;
#pragma unroll 8
            for (int k = 0; k < AT; ++k) {
                float pv = pr[k];
                float e = (pv <= -1e29f) ? 0.f : __expf(pv - mn);
                pr[k] = e;
                srow += e;
            }
            lrow[tid] = lrow[tid] * c + srow;
            mrow[tid] = mn;
            crow[tid] = c;
        }
        __syncthreads();

        // O = O*c + P @ V
        float ci[4];
#pragma unroll
        for (int i = 0; i < 4; ++i) ci[i] = crow[ty4 + i];
#pragma unroll
        for (int i = 0; i < 4; ++i)
#pragma unroll
            for (int j = 0; j < 4; ++j) o[i][j] *= ci[i];
#pragma unroll 8
        for (int k = 0; k < AT; ++k) {
            float p[4], vv[4];
#pragma unroll
            for (int i = 0; i < 4; ++i) p[i] = Ps[(ty4 + i) * APAD + k];
#pragma unroll
            for (int j = 0; j < 4; ++j) vv[j] = Vs[k * APAD + tx4 + j];
#pragma unroll
            for (int i = 0; i < 4; ++i)
#pragma unroll
                for (int j = 0; j < 4; ++j)
                    o[i][j] = fmaf(p[i], vv[j], o[i][j]);
        }
        __syncthreads();
    }

    // write O / l   (out layout: [n, q, h, d] flattened to [TOK, DIM])
#pragma unroll
    for (int i = 0; i < 4; ++i) {
        int q = q0 + ty4 + i;
        if (q < SEQL) {
            float inv = 1.0f / lrow[ty4 + i];
#pragma unroll
            for (int j = 0; j < 4; ++j)
                out[((size_t)n * SEQL + q) * DIM + h * DH + tx4 + j] = o[i][j] * inv;
        }
    }
}

#define ATT_SMEM ((4 * AT * APAD + 5 * AT) * (int)sizeof(float))

// ---------------- orchestration ----------------
extern "C" void kernel_launch(void* const* d_in, const int* in_sizes, int n_in,
                              void* d_out, int out_size)
{
    (void)in_sizes; (void)n_in; (void)out_size;
    const float* patch    = (const float*)d_in[0];
    const int*   done     = (const int*)  d_in[1];
    const float* W_embed  = (const float*)d_in[2];
    const float* b_embed  = (const float*)d_in[3];
    const float* spatial  = (const float*)d_in[4];
    const float* temporal = (const float*)d_in[5];
    const float* ln1_g    = (const float*)d_in[6];
    const float* ln1_b    = (const float*)d_in[7];
    const float* Wqkv     = (const float*)d_in[8];
    const float* bqkv     = (const float*)d_in[9];
    const float* Wo       = (const float*)d_in[10];
    const float* bo       = (const float*)d_in[11];
    const float* ln2_g    = (const float*)d_in[12];
    const float* ln2_b    = (const float*)d_in[13];
    const float* W1       = (const float*)d_in[14];
    const float* b1       = (const float*)d_in[15];
    const float* W2       = (const float*)d_in[16];
    const float* b2       = (const float*)d_in[17];
    const float* out_g    = (const float*)d_in[18];
    const float* out_b    = (const float*)d_in[19];
    float* out = (float*)d_out;

    float *x, *h, *qkv, *att, *mlp, *keep;
    cudaGetSymbolAddress((void**)&x,    g_x);
    cudaGetSymbolAddress((void**)&h,    g_h);
    cudaGetSymbolAddress((void**)&qkv,  g_qkv);
    cudaGetSymbolAddress((void**)&att,  g_att);
    cudaGetSymbolAddress((void**)&mlp,  g_mlp);
    cudaGetSymbolAddress((void**)&keep, g_keep);

    cudaFuncSetAttribute(attn_kernel, cudaFuncAttributeMaxDynamicSharedMemorySize, ATT_SMEM);

    keep_kernel<<<1, 32>>>(done, keep);

    // patch embed + pos embed
    sgemm_kernel<<<dim3(DIM / 128, TOK / 128), 256>>>(
        patch, W_embed, b_embed, nullptr, x, TOK, DIM, PDIM, EPI_EMBED, spatial, temporal);

    for (int i = 0; i < DEPTH; ++i) {
        ln_kernel<<<TOK, 128>>>(x, ln1_g + (size_t)i * DIM, ln1_b + (size_t)i * DIM, h);

        sgemm_kernel<<<dim3(3 * DIM / 128, TOK / 128), 256>>>(
            h, Wqkv + (size_t)i * DIM * 3 * DIM, bqkv + (size_t)i * 3 * DIM,
            nullptr, qkv, TOK, 3 * DIM, DIM, EPI_NONE, nullptr, nullptr);

        attn_kernel<<<dim3((SEQL + AT - 1) / AT, HEADS, NB), 256, ATT_SMEM>>>(qkv, keep, att);

        sgemm_kernel<<<dim3(DIM / 128, TOK / 128), 256>>>(
            att, Wo + (size_t)i * DIM * DIM, bo + (size_t)i * DIM,
            x, x, TOK, DIM, DIM, EPI_RES, nullptr, nullptr);

        ln_kernel<<<TOK, 128>>>(x, ln2_g + (size_t)i * DIM, ln2_b + (size_t)i * DIM, h);

        sgemm_kernel<<<dim3(MLPD / 128, TOK / 128), 256>>>(
            h, W1 + (size_t)i * DIM * MLPD, b1 + (size_t)i * MLPD,
            nullptr, mlp, TOK, MLPD, DIM, EPI_GELU, nullptr, nullptr);

        sgemm_kernel<<<dim3(DIM / 128, TOK / 128), 256>>>(
            mlp, W2 + (size_t)i * MLPD * DIM, b2 + (size_t)i * DIM,
            x, x, TOK, DIM, MLPD, EPI_RES, nullptr, nullptr);
    }

    ln_kernel<<<TOK, 128>>>(x, out_g, out_b, out);
}

// round 2
// speedup vs baseline: 1.0634x; 1.0634x over previous
#include <cuda_runtime.h>
#include <cstdint>
#include <cstddef>

// ---------------- problem constants ----------------
#define NB      32
#define T_STEP  16
#define NPATCH  49
#define SEQL    784            // T_STEP * NPATCH
#define TOK     25088          // NB * SEQL
#define DIM     512
#define HEADS   8
#define DH      64
#define MLPD    2048
#define PDIM    432
#define DEPTH   4

// ---------------- scratch (device globals; no allocations allowed) ----------------
__device__ float g_x  [(size_t)TOK * DIM];
__device__ float g_h  [(size_t)TOK * DIM];
__device__ float g_qkv[(size_t)TOK * 3 * DIM];
__device__ float g_att[(size_t)TOK * DIM];
__device__ float g_mlp[(size_t)TOK * MLPD];
__device__ float g_keep[(size_t)NB * SEQL];

// ---------------- epilogue modes ----------------
#define EPI_NONE  0
#define EPI_EMBED 1
#define EPI_RES   2
#define EPI_GELU  3

// ---------------- mask kernel ----------------
__global__ void keep_kernel(const int* __restrict__ done, float* __restrict__ keep)
{
    int n = threadIdx.x;
    if (n >= NB) return;
    float kv[T_STEP];
    int flag = 0;
    for (int t = T_STEP - 2; t >= 0; --t) {
        flag |= done[n * (T_STEP - 1) + t];
        kv[t] = flag ? 0.f : 1.f;
    }
    kv[T_STEP - 1] = 1.f;
    for (int t = 0; t < T_STEP; ++t) {
        float v = kv[t];
        for (int p = 0; p < NPATCH; ++p)
            keep[(size_t)n * SEQL + t * NPATCH + p] = v;
    }
}

// ---------------- tf32 helpers ----------------
__device__ __forceinline__ uint32_t f2tf32(float x) {
    uint32_t u;
    asm("cvt.rna.tf32.f32 %0, %1;" : "=r"(u) : "f"(x));
    return u;
}

__device__ __forceinline__ void mma_tf32(float c[4], const uint32_t a[4], const uint32_t b[2]) {
    asm volatile(
        "mma.sync.aligned.m16n8k8.row.col.f32.tf32.tf32.f32 "
        "{%0,%1,%2,%3}, {%4,%5,%6,%7}, {%8,%9}, {%0,%1,%2,%3};\n"
        : "+f"(c[0]), "+f"(c[1]), "+f"(c[2]), "+f"(c[3])
        : "r"(a[0]), "r"(a[1]), "r"(a[2]), "r"(a[3]), "r"(b[0]), "r"(b[1]));
}

// ---------------- tensor-core GEMM: C = A[MxK] @ B[KxN] + bias, fused epilogue ----
// 128x128 CTA tile, BK=16, 128 threads (4 warps, each 64x64 warp tile).
// A/B staged in shared memory in FRAGMENT-MAJOR order so fragment loads are
// vectorized (LDS.128 for A, LDS.64 for B) and conflict-free.
// Requires M%128==0, N%128==0, K%16==0.
__global__ __launch_bounds__(128, 2)
void tgemm_kernel(const float* __restrict__ A, const float* __restrict__ B,
                  const float* __restrict__ bias, const float* __restrict__ res,
                  float* __restrict__ C, int M, int N, int K, int epi,
                  const float* __restrict__ sp, const float* __restrict__ tp)
{
    __shared__ uint32_t As[2048];   // [ks][mt][lane][slot] : 2*8*32*4
    __shared__ uint32_t Bs[2048];   // [ks][nt][lane][slot] : 2*16*32*2

    const int tid = threadIdx.x;
    const int lane = tid & 31;
    const int wid = tid >> 5;
    const int warp_m = wid >> 1;    // 0..1
    const int warp_n = wid & 1;     // 0..1
    const int bx = blockIdx.x;      // N tile
    const int by = blockIdx.y;      // M tile

    // A loader: thread covers rows m = (tid>>2) + it*32, cols k4..k4+3
    const int a_m = tid >> 2;            // 0..31
    const int a_k4 = (tid & 3) * 4;      // 0,4,8,12
    // B loader: rows k = (tid>>5) + it*4, cols n4..n4+3
    const int b_k = tid >> 5;            // 0..3
    const int b_n4 = (tid & 31) * 4;     // 0..124

    const float* Abase = A + (size_t)(by * 128) * K;
    const float* Bbase = B + bx * 128;

    float c[4][8][4];
#pragma unroll
    for (int mt = 0; mt < 4; ++mt)
#pragma unroll
        for (int nt = 0; nt < 8; ++nt)
#pragma unroll
            for (int e = 0; e < 4; ++e) c[mt][nt][e] = 0.f;

    const int niter = K >> 4;

    float4 ra[4], rb[4];

    // prologue: load tile 0
#pragma unroll
    for (int it = 0; it < 4; ++it) {
        int m = a_m + it * 32;
        ra[it] = *(const float4*)(Abase + (size_t)m * K + a_k4);
        int k = b_k + it * 4;
        rb[it] = *(const float4*)(Bbase + (size_t)k * N + b_n4);
    }

    for (int i = 0; i < niter; ++i) {
        // scatter regs -> smem (fragment-major, tf32-converted)
#pragma unroll
        for (int it = 0; it < 4; ++it) {
            int m = a_m + it * 32;
            int mt = m >> 4;
            int mbit = (m >> 3) & 1;
            int lt = (m & 7) * 4;
            float av[4] = {ra[it].x, ra[it].y, ra[it].z, ra[it].w};
#pragma unroll
            for (int d = 0; d < 4; ++d) {
                int k = a_k4 + d;
                int ks = k >> 3;
                int slot = mbit + (((k >> 2) & 1) << 1);
                As[((ks * 8 + mt) * 32 + lt + d) * 4 + slot] = f2tf32(av[d]);
            }
            int kk = b_k + it * 4;
            int ks2 = kk >> 3;
            int slot2 = (kk >> 2) & 1;
            int klow = kk & 3;
            float bv[4] = {rb[it].x, rb[it].y, rb[it].z, rb[it].w};
#pragma unroll
            for (int d = 0; d < 4; ++d) {
                int n = b_n4 + d;
                int nt = n >> 3;
                Bs[((ks2 * 16 + nt) * 32 + (n & 7) * 4 + klow) * 2 + slot2] = f2tf32(bv[d]);
            }
        }
        __syncthreads();

        // prefetch next tile into registers (hidden behind the MMAs below)
        if (i + 1 < niter) {
            int k0 = (i + 1) << 4;
#pragma unroll
            for (int it = 0; it < 4; ++it) {
                int m = a_m + it * 32;
                ra[it] = *(const float4*)(Abase + (size_t)m * K + k0 + a_k4);
                int k = b_k + it * 4;
                rb[it] = *(const float4*)(Bbase + (size_t)(k0 + k) * N + b_n4);
            }
        }

        // compute: 2 k-steps of 8, 32 MMAs each warp per k-step
#pragma unroll
        for (int ks = 0; ks < 2; ++ks) {
            uint32_t af[4][4];
            uint32_t bf[8][2];
#pragma unroll
            for (int mt = 0; mt < 4; ++mt) {
                *(uint4*)af[mt] =
                    *(const uint4*)&As[((ks * 8 + warp_m * 4 + mt) * 32 + lane) * 4];
            }
#pragma unroll
            for (int nt = 0; nt < 8; ++nt) {
                *(uint2*)bf[nt] =
                    *(const uint2*)&Bs[((ks * 16 + warp_n * 8 + nt) * 32 + lane) * 2];
            }
#pragma unroll
            for (int mt = 0; mt < 4; ++mt)
#pragma unroll
                for (int nt = 0; nt < 8; ++nt)
                    mma_tf32(c[mt][nt], af[mt], bf[nt]);
        }
        __syncthreads();
    }

    // -------- epilogue --------
    const int r_base = by * 128 + warp_m * 64;
    const int c_base = bx * 128 + warp_n * 64;
    const int rl = lane >> 2;          // 0..7
    const int cl = (lane & 3) * 2;     // 0,2,4,6

#pragma unroll
    for (int mt = 0; mt < 4; ++mt) {
#pragma unroll
        for (int half = 0; half < 2; ++half) {
            const int r = r_base + mt * 16 + rl + half * 8;
            const int l = r % SEQL;
            const int tt = l / NPATCH;
            const int pp = l % NPATCH;
#pragma unroll
            for (int nt = 0; nt < 8; ++nt) {
                const int col = c_base + nt * 8 + cl;
                float v0 = c[mt][nt][half * 2 + 0] + bias[col];
                float v1 = c[mt][nt][half * 2 + 1] + bias[col + 1];
                if (epi == EPI_EMBED) {
                    v0 += sp[(size_t)pp * DIM + col]     + tp[(size_t)tt * DIM + col];
                    v1 += sp[(size_t)pp * DIM + col + 1] + tp[(size_t)tt * DIM + col + 1];
                } else if (epi == EPI_RES) {
                    v0 += res[(size_t)r * N + col];
                    v1 += res[(size_t)r * N + col + 1];
                } else if (epi == EPI_GELU) {
                    v0 = 0.5f * v0 * (1.0f + erff(v0 * 0.70710678118654752f));
                    v1 = 0.5f * v1 * (1.0f + erff(v1 * 0.70710678118654752f));
                }
                float2 o2 = make_float2(v0, v1);
                *(float2*)(C + (size_t)r * N + col) = o2;
            }
        }
    }
}

// ---------------- LayerNorm: one block (128 thr) per row of 512 ----------------
__global__ void ln_kernel(const float* __restrict__ x, const float* __restrict__ g,
                          const float* __restrict__ b, float* __restrict__ y)
{
    const int row = blockIdx.x;
    const int tid = threadIdx.x;   // 128
    const float4 v = *(const float4*)(x + (size_t)row * DIM + tid * 4);

    __shared__ float red[4];
    float s = v.x + v.y + v.z + v.w;
#pragma unroll
    for (int o = 16; o > 0; o >>= 1) s += __shfl_xor_sync(0xffffffffu, s, o);
    if ((tid & 31) == 0) red[tid >> 5] = s;
    __syncthreads();
    const float mean = (red[0] + red[1] + red[2] + red[3]) * (1.0f / DIM);

    const float d0 = v.x - mean, d1 = v.y - mean, d2 = v.z - mean, d3 = v.w - mean;
    float q = d0 * d0 + d1 * d1 + d2 * d2 + d3 * d3;
    __syncthreads();
#pragma unroll
    for (int o = 16; o > 0; o >>= 1) q += __shfl_xor_sync(0xffffffffu, q, o);
    if ((tid & 31) == 0) red[tid >> 5] = q;
    __syncthreads();
    const float var = (red[0] + red[1] + red[2] + red[3]) * (1.0f / DIM);
    const float rs = rsqrtf(var + 1e-5f);

    const float4 gv = *(const float4*)(g + tid * 4);
    const float4 bv = *(const float4*)(b + tid * 4);
    float4 o4;
    o4.x = d0 * rs * gv.x + bv.x;
    o4.y = d1 * rs * gv.y + bv.y;
    o4.z = d2 * rs * gv.z + bv.z;
    o4.w = d3 * rs * gv.w + bv.w;
    *(float4*)(y + (size_t)row * DIM + tid * 4) = o4;
}

// ---------------- flash-style attention ----------------
// grid (13, HEADS, NB), 256 threads. 64-query CTA tile, 64-key KV tiles.
// Mask semantics (matching the fp32 reference with -1e9 bias):
//   keep_q == 1: attend only to keys with keep_k == 1 (others weight exactly 0)
//   keep_q == 0: -1e9 is added to EVERY score, which in fp32 collapses all scores to
//                exactly -1e9 -> softmax is exactly UNIFORM over all 784 keys.
#define AT   64
#define APAD 68
__global__ __launch_bounds__(256)
void attn_kernel(const float* __restrict__ qkv, const float* __restrict__ keep,
                 float* __restrict__ out)
{
    extern __shared__ float sm[];
    float* Qt   = sm;                    // [64][APAD]  d-major (Qt[d][q])
    float* Kt   = Qt + AT * APAD;        // [64][APAD]  d-major (Kt[d][k])
    float* Vs   = Kt + AT * APAD;        // [64][APAD]  token-major (Vs[k][d])
    float* Ps   = Vs + AT * APAD;        // [64][APAD]
    float* mrow = Ps + AT * APAD;        // [64]
    float* lrow = mrow + AT;
    float* crow = lrow + AT;
    float* kqs  = crow + AT;             // keep_q per row
    float* kks  = kqs + AT;              // keep_k per col

    const int qt = blockIdx.x;
    const int h  = blockIdx.y;
    const int n  = blockIdx.z;
    const int tid = threadIdx.x;
    const int tx = tid & 15;
    const int ty = tid >> 4;
    const int tx4 = tx * 4, ty4 = ty * 4;
    const int q0 = qt * AT;

    const float* base = qkv + (size_t)n * SEQL * (3 * DIM);

    // load Q tile (transposed into Qt[d][q])
#pragma unroll
    for (int it = 0; it < 4; ++it) {
        int idx = tid + it * 256;
        int row = idx >> 4;
        int cg  = (idx & 15) * 4;
        int qrow = q0 + row;
        int src = qrow < SEQL ? qrow : (SEQL - 1);
        float4 v = *(const float4*)(base + (size_t)src * (3 * DIM) + h * DH + cg);
        Qt[(cg + 0) * APAD + row] = v.x;
        Qt[(cg + 1) * APAD + row] = v.y;
        Qt[(cg + 2) * APAD + row] = v.z;
        Qt[(cg + 3) * APAD + row] = v.w;
    }
    if (tid < AT) {
        int qrow = q0 + tid;
        kqs[tid] = (qrow < SEQL) ? keep[(size_t)n * SEQL + qrow] : 0.f;
        mrow[tid] = -1e30f;
        lrow[tid] = 0.f;
    }
    float o[4][4];
#pragma unroll
    for (int i = 0; i < 4; ++i)
#pragma unroll
        for (int j = 0; j < 4; ++j) o[i][j] = 0.f;
    __syncthreads();

    float kqv[4];
#pragma unroll
    for (int i = 0; i < 4; ++i) kqv[i] = kqs[ty4 + i];

    for (int kt0 = 0; kt0 < SEQL; kt0 += AT) {
        // load K (transposed) and V (natural)
#pragma unroll
        for (int it = 0; it < 4; ++it) {
            int idx = tid + it * 256;
            int row = idx >> 4;
            int cg  = (idx & 15) * 4;
            int krow = kt0 + row;
            int src = krow < SEQL ? krow : (SEQL - 1);
            const float* kp = base + (size_t)src * (3 * DIM) + DIM + h * DH + cg;
            float4 k4 = *(const float4*)kp;
            Kt[(cg + 0) * APAD + row] = k4.x;
            Kt[(cg + 1) * APAD + row] = k4.y;
            Kt[(cg + 2) * APAD + row] = k4.z;
            Kt[(cg + 3) * APAD + row] = k4.w;
            const float* vp = base + (size_t)src * (3 * DIM) + 2 * DIM + h * DH + cg;
            float4 v4 = *(const float4*)vp;
            *(float4*)&Vs[row * APAD + cg] = v4;
        }
        if (tid < AT)
            kks[tid] = (kt0 + tid < SEQL) ? keep[(size_t)n * SEQL + kt0 + tid] : 0.f;
        __syncthreads();

        // S = Q @ K^T (4x4 per thread)
        float s[4][4];
#pragma unroll
        for (int i = 0; i < 4; ++i)
#pragma unroll
            for (int j = 0; j < 4; ++j) s[i][j] = 0.f;
#pragma unroll 8
        for (int d = 0; d < DH; ++d) {
            float a[4], bb[4];
#pragma unroll
            for (int i = 0; i < 4; ++i) a[i] = Qt[d * APAD + ty4 + i];
#pragma unroll
            for (int j = 0; j < 4; ++j) bb[j] = Kt[d * APAD + tx4 + j];
#pragma unroll
            for (int i = 0; i < 4; ++i)
#pragma unroll
                for (int j = 0; j < 4; ++j)
                    s[i][j] = fmaf(a[i], bb[j], s[i][j]);
        }

        // mask/scale and write P
#pragma unroll
        for (int i = 0; i < 4; ++i) {
#pragma unroll
            for (int j = 0; j < 4; ++j) {
                int kidx = kt0 + tx4 + j;
                float val;
                if (kidx >= SEQL) {
                    val = -1e30f;
                } else if (kqv[i] > 0.5f) {
                    val = (kks[tx4 + j] > 0.5f) ? s[i][j] * 0.125f : -1e30f;
                } else {
                    val = 0.f;   // fully-masked row -> uniform softmax
                }
                Ps[(ty4 + i) * APAD + tx4 + j] = val;
            }
        }
        __syncthreads();

        // online softmax per row (rows handled by threads 0..63)
        if (tid < AT) {
            float* pr = Ps + tid * APAD;
            float mo = mrow[tid];
            float tm = -1e30f;
#pragma unroll 8
            for (int k = 0; k < AT; ++k) tm = fmaxf(tm, pr[k]);
            float mn = fmaxf(mo, tm);
            float c = __expf(mo - mn);     // mo==mn==-1e30 -> 1, O is 0 anyway
            float srow = 0.f;
#pragma unroll 8
            for (int k = 0; k < AT; ++k) {
                float pv = pr[k];
                float e = (pv <= -1e29f) ? 0.f : __expf(pv - mn);
                pr[k] = e;
                srow += e;
            }
            lrow[tid] = lrow[tid] * c + srow;
            mrow[tid] = mn;
            crow[tid] = c;
        }
        __syncthreads();

        // O = O*c + P @ V
        float ci[4];
#pragma unroll
        for (int i = 0; i < 4; ++i) ci[i] = crow[ty4 + i];
#pragma unroll
        for (int i = 0; i < 4; ++i)
#pragma unroll
            for (int j = 0; j < 4; ++j) o[i][j] *= ci[i];
#pragma unroll 8
        for (int k = 0; k < AT; ++k) {
            float p[4], vv[4];
#pragma unroll
            for (int i = 0; i < 4; ++i) p[i] = Ps[(ty4 + i) * APAD + k];
#pragma unroll
            for (int j = 0; j < 4; ++j) vv[j] = Vs[k * APAD + tx4 + j];
#pragma unroll
            for (int i = 0; i < 4; ++i)
#pragma unroll
                for (int j = 0; j < 4; ++j)
                    o[i][j] = fmaf(p[i], vv[j], o[i][j]);
        }
        __syncthreads();
    }

    // write O / l   (out layout: [n, q, h, d] flattened to [TOK, DIM])
#pragma unroll
    for (int i = 0; i < 4; ++i) {
        int q = q0 + ty4 + i;
        if (q < SEQL) {
            float inv = 1.0f / lrow[ty4 + i];
#pragma unroll
            for (int j = 0; j < 4; ++j)
                out[((size_t)n * SEQL + q) * DIM + h * DH + tx4 + j] = o[i][j] * inv;
        }
    }
}

#define ATT_SMEM ((4 * AT * APAD + 5 * AT) * (int)sizeof(float))

// ---------------- orchestration ----------------
extern "C" void kernel_launch(void* const* d_in, const int* in_sizes, int n_in,
                              void* d_out, int out_size)
{
    (void)in_sizes; (void)n_in; (void)out_size;
    const float* patch    = (const float*)d_in[0];
    const int*   done     = (const int*)  d_in[1];
    const float* W_embed  = (const float*)d_in[2];
    const float* b_embed  = (const float*)d_in[3];
    const float* spatial  = (const float*)d_in[4];
    const float* temporal = (const float*)d_in[5];
    const float* ln1_g    = (const float*)d_in[6];
    const float* ln1_b    = (const float*)d_in[7];
    const float* Wqkv     = (const float*)d_in[8];
    const float* bqkv     = (const float*)d_in[9];
    const float* Wo       = (const float*)d_in[10];
    const float* bo       = (const float*)d_in[11];
    const float* ln2_g    = (const float*)d_in[12];
    const float* ln2_b    = (const float*)d_in[13];
    const float* W1       = (const float*)d_in[14];
    const float* b1       = (const float*)d_in[15];
    const float* W2       = (const float*)d_in[16];
    const float* b2       = (const float*)d_in[17];
    const float* out_g    = (const float*)d_in[18];
    const float* out_b    = (const float*)d_in[19];
    float* out = (float*)d_out;

    float *x, *h, *qkv, *att, *mlp, *keep;
    cudaGetSymbolAddress((void**)&x,    g_x);
    cudaGetSymbolAddress((void**)&h,    g_h);
    cudaGetSymbolAddress((void**)&qkv,  g_qkv);
    cudaGetSymbolAddress((void**)&att,  g_att);
    cudaGetSymbolAddress((void**)&mlp,  g_mlp);
    cudaGetSymbolAddress((void**)&keep, g_keep);

    cudaFuncSetAttribute(attn_kernel, cudaFuncAttributeMaxDynamicSharedMemorySize, ATT_SMEM);

    keep_kernel<<<1, 32>>>(done, keep);

    // patch embed + pos embed
    tgemm_kernel<<<dim3(DIM / 128, TOK / 128), 128>>>(
        patch, W_embed, b_embed, nullptr, x, TOK, DIM, PDIM, EPI_EMBED, spatial, temporal);

    for (int i = 0; i < DEPTH; ++i) {
        ln_kernel<<<TOK, 128>>>(x, ln1_g + (size_t)i * DIM, ln1_b + (size_t)i * DIM, h);

        tgemm_kernel<<<dim3(3 * DIM / 128, TOK / 128), 128>>>(
            h, Wqkv + (size_t)i * DIM * 3 * DIM, bqkv + (size_t)i * 3 * DIM,
            nullptr, qkv, TOK, 3 * DIM, DIM, EPI_NONE, nullptr, nullptr);

        attn_kernel<<<dim3((SEQL + AT - 1) / AT, HEADS, NB), 256, ATT_SMEM>>>(qkv, keep, att);

        tgemm_kernel<<<dim3(DIM / 128, TOK / 128), 128>>>(
            att, Wo + (size_t)i * DIM * DIM, bo + (size_t)i * DIM,
            x, x, TOK, DIM, DIM, EPI_RES, nullptr, nullptr);

        ln_kernel<<<TOK, 128>>>(x, ln2_g + (size_t)i * DIM, ln2_b + (size_t)i * DIM, h);

        tgemm_kernel<<<dim3(MLPD / 128, TOK / 128), 128>>>(
            h, W1 + (size_t)i * DIM * MLPD, b1 + (size_t)i * MLPD,
            nullptr, mlp, TOK, MLPD, DIM, EPI_GELU, nullptr, nullptr);

        tgemm_kernel<<<dim3(DIM / 128, TOK / 128), 128>>>(
            mlp, W2 + (size_t)i * MLPD * DIM, b2 + (size_t)i * DIM,
            x, x, TOK, DIM, MLPD, EPI_RES, nullptr, nullptr);
    }

    ln_kernel<<<TOK, 128>>>(x, out_g, out_b, out);
}

// round 4
// speedup vs baseline: 2.0226x; 1.9019x over previous
#include <cuda_runtime.h>
#include <cstdint>
#include <cstddef>

// ---------------- problem constants ----------------
#define NB      32
#define T_STEP  16
#define NPATCH  49
#define SEQL    784            // T_STEP * NUM_PATCHES
#define TOK     25088          // NB * SEQL
#define DIM     512
#define HEADS   8
#define DH      64
#define MLPD    2048
#define PDIM    432
#define DEPTH   4

// ---------------- scratch (device globals; no allocations allowed) ----------------
__device__ float g_x  [(size_t)TOK * DIM];
__device__ float g_h  [(size_t)TOK * DIM];
__device__ float g_qkv[(size_t)TOK * 3 * DIM];
__device__ float g_att[(size_t)TOK * DIM];
__device__ float g_mlp[(size_t)TOK * MLPD];
__device__ float g_keep[(size_t)NB * SEQL];

// transposed weights  [N][K] layouts
#define OFF_QKVT 0
#define OFF_WOT  3145728
#define OFF_W1T  4194304
#define OFF_W2T  8388608
#define OFF_WEBT 12582912
__device__ float g_wT[12804096];

// ---------------- epilogue modes ----------------
#define EPI_NONE  0
#define EPI_EMBED 1
#define EPI_RES   2
#define EPI_GELU  3

// ---------------- helpers ----------------
__device__ __forceinline__ uint32_t smem_u32(const void* p) {
    uint32_t a;
    asm("{ .reg .u64 t; cvta.to.shared.u64 t, %1; cvt.u32.u64 %0, t; }" : "=r"(a) : "l"(p));
    return a;
}

__device__ __forceinline__ uint32_t f2tf32(float x) {
    uint32_t u;
    asm("cvt.rna.tf32.f32 %0, %1;" : "=r"(u) : "f"(x));
    return u;
}

__device__ __forceinline__ void mma_tf32(float c[4], const uint32_t a[4], const uint32_t b[2]) {
    asm volatile(
        "mma.sync.aligned.m16n8k8.row.col.f32.tf32.tf32.f32 "
        "{%0,%1,%2,%3}, {%4,%5,%6,%7}, {%8,%9}, {%0,%1,%2,%3};\n"
        : "+f"(c[0]), "+f"(c[1]), "+f"(c[2]), "+f"(c[3])
        : "r"(a[0]), "r"(a[1]), "r"(a[2]), "r"(a[3]), "r"(b[0]), "r"(b[1]));
}

__device__ __forceinline__ void ldsm_x4(uint32_t& r0, uint32_t& r1, uint32_t& r2,
                                        uint32_t& r3, uint32_t addr) {
    asm volatile("ldmatrix.sync.aligned.m8n8.x4.shared.b16 {%0,%1,%2,%3}, [%4];"
                 : "=r"(r0), "=r"(r1), "=r"(r2), "=r"(r3) : "r"(addr));
}

// swizzled 16B-unit offset within an operand tile: rows of 16 tf32 (4 x 16B units)
// off16(m, q) = m*4 + (q ^ ((m>>1)&3)); conflict-free for both STS.128 and ldmatrix.
__device__ __forceinline__ uint32_t swz16(int m, int q) {
    return (uint32_t)(m * 4 + (q ^ ((m >> 1) & 3)));
}

// ---------------- mask kernel ----------------
__global__ void keep_kernel(const int* __restrict__ done, float* __restrict__ keep)
{
    int n = threadIdx.x;
    if (n >= NB) return;
    float kv[T_STEP];
    int flag = 0;
    for (int t = T_STEP - 2; t >= 0; --t) {
        flag |= done[n * (T_STEP - 1) + t];
        kv[t] = flag ? 0.f : 1.f;
    }
    kv[T_STEP - 1] = 1.f;
    for (int t = 0; t < T_STEP; ++t) {
        float v = kv[t];
        for (int p = 0; p < NPATCH; ++p)
            keep[(size_t)n * SEQL + t * NPATCH + p] = v;
    }
}

// ---------------- weight transpose: src[K][N] -> dst[N][K] ----------------
__global__ void transpose_kernel(const float* __restrict__ src, float* __restrict__ dst,
                                 int K, int N)
{
    __shared__ float t[32][33];
    int x = blockIdx.x * 32 + threadIdx.x;   // n
    int y = blockIdx.y * 32 + threadIdx.y;   // k
#pragma unroll
    for (int j = 0; j < 32; j += 8)
        if (x < N && y + j < K)
            t[threadIdx.y + j][threadIdx.x] = src[(size_t)(y + j) * N + x];
    __syncthreads();
    x = blockIdx.y * 32 + threadIdx.x;       // k
    y = blockIdx.x * 32 + threadIdx.y;       // n
#pragma unroll
    for (int j = 0; j < 32; j += 8)
        if (x < K && y + j < N)
            dst[(size_t)(y + j) * K + x] = t[threadIdx.x][threadIdx.y + j];
}

// ---------------- tf32 mma.sync GEMM with ldmatrix: C = A @ Bt^T + bias ----------
// 128x128 CTA tile, BK=16, 256 threads, 8 warps as 2(m) x 4(n), warp tile 64x32.
// A smem [128][16] tf32 rows (64B), B smem [128][16]; swizzled; STS.128 in,
// ldmatrix.x4 out. Requires M%128==0, N%128==0, K%16==0.
__global__ __launch_bounds__(256, 2)
void tgemm_kernel(const float* __restrict__ A, const float* __restrict__ Bt,
                  const float* __restrict__ bias, const float* __restrict__ res,
                  float* __restrict__ C, int M, int N, int K, int epi,
                  const float* __restrict__ sp, const float* __restrict__ tp)
{
    __shared__ uint32_t As[2048];   // 128 rows x 16 tf32
    __shared__ uint32_t Bs[2048];

    const int tid = threadIdx.x;
    const int lane = tid & 31;
    const int wid = tid >> 5;
    const int warp_m = wid >> 2;    // 0..1
    const int warp_n = wid & 3;     // 0..3
    const int n0 = blockIdx.x * 128;
    const int m0 = blockIdx.y * 128;

    // loaders: each thread handles rows (tid>>2) and (tid>>2)+64, k-quad tid&3
    const int l_m = tid >> 2;        // 0..63
    const int l_q = tid & 3;         // 16B unit within row

    const uint32_t sA = smem_u32(As);
    const uint32_t sB = smem_u32(Bs);
    const uint32_t stsA0 = sA + swz16(l_m, l_q) * 16;
    const uint32_t stsA1 = sA + swz16(l_m + 64, l_q) * 16;
    const uint32_t stsB0 = sB + swz16(l_m, l_q) * 16;
    const uint32_t stsB1 = sB + swz16(l_m + 64, l_q) * 16;

    const float* Ap0 = A + (size_t)(m0 + l_m) * K + l_q * 4;
    const float* Ap1 = A + (size_t)(m0 + l_m + 64) * K + l_q * 4;
    const float* Bp0 = Bt + (size_t)(n0 + l_m) * K + l_q * 4;
    const float* Bp1 = Bt + (size_t)(n0 + l_m + 64) * K + l_q * 4;

    // fragment ldmatrix addressing
    const int g = lane >> 3;         // matrix group 0..3
    const int r = lane & 7;
    // A: matrices {m rows, kq0}, {m+8, kq0}, {m, kq1}, {m+8, kq1}
    const int a_mrow0 = warp_m * 64 + (g & 1) * 8 + r;   // + mt*16
    const int a_kq = g >> 1;                              // 0/1, + ks*2
    // B: matrices {n rows, kq0}, {n, kq1}, {n+8, kq0}, {n+8, kq1}
    const int b_nrow0 = warp_n * 32 + (g >> 1) * 8 + r;  // + p*16
    const int b_kq = g & 1;                               // 0/1, + ks*2

    float acc[4][4][4];
#pragma unroll
    for (int mt = 0; mt < 4; ++mt)
#pragma unroll
        for (int nt = 0; nt < 4; ++nt)
#pragma unroll
            for (int e = 0; e < 4; ++e) acc[mt][nt][e] = 0.f;

    const int niter = K >> 4;

    float4 ra0, ra1, rb0, rb1;
    ra0 = *(const float4*)Ap0;
    ra1 = *(const float4*)Ap1;
    rb0 = *(const float4*)Bp0;
    rb1 = *(const float4*)Bp1;

    for (int i = 0; i < niter; ++i) {
        // STS.128 converted tiles
        uint4 u;
        u.x = f2tf32(ra0.x); u.y = f2tf32(ra0.y); u.z = f2tf32(ra0.z); u.w = f2tf32(ra0.w);
        *(uint4*)(As + (stsA0 - sA) / 4) = u;
        u.x = f2tf32(ra1.x); u.y = f2tf32(ra1.y); u.z = f2tf32(ra1.z); u.w = f2tf32(ra1.w);
        *(uint4*)(As + (stsA1 - sA) / 4) = u;
        u.x = f2tf32(rb0.x); u.y = f2tf32(rb0.y); u.z = f2tf32(rb0.z); u.w = f2tf32(rb0.w);
        *(uint4*)(Bs + (stsB0 - sB) / 4) = u;
        u.x = f2tf32(rb1.x); u.y = f2tf32(rb1.y); u.z = f2tf32(rb1.z); u.w = f2tf32(rb1.w);
        *(uint4*)(Bs + (stsB1 - sB) / 4) = u;
        __syncthreads();

        // prefetch next k-slab
        if (i + 1 < niter) {
            const int ko = (i + 1) * 16;
            ra0 = *(const float4*)(Ap0 + ko);
            ra1 = *(const float4*)(Ap1 + ko);
            rb0 = *(const float4*)(Bp0 + ko);
            rb1 = *(const float4*)(Bp1 + ko);
        }

        // compute 2 k-steps of 8
#pragma unroll
        for (int ks = 0; ks < 2; ++ks) {
            uint32_t af[4][4];
            uint32_t bf[4][2];
#pragma unroll
            for (int mt = 0; mt < 4; ++mt) {
                const int mrow = a_mrow0 + mt * 16;
                const uint32_t addr = sA + swz16(mrow, ks * 2 + a_kq) * 16;
                ldsm_x4(af[mt][0], af[mt][1], af[mt][2], af[mt][3], addr);
            }
#pragma unroll
            for (int p = 0; p < 2; ++p) {
                const int nrow = b_nrow0 + p * 16;
                const uint32_t addr = sB + swz16(nrow, ks * 2 + b_kq) * 16;
                ldsm_x4(bf[p * 2][0], bf[p * 2][1], bf[p * 2 + 1][0], bf[p * 2 + 1][1], addr);
            }
#pragma unroll
            for (int mt = 0; mt < 4; ++mt)
#pragma unroll
                for (int nt = 0; nt < 4; ++nt)
                    mma_tf32(acc[mt][nt], af[mt], bf[nt]);
        }
        __syncthreads();
    }

    // -------- epilogue --------
    const int r_base = m0 + warp_m * 64;
    const int c_base = n0 + warp_n * 32;
    const int rl = lane >> 2;          // 0..7
    const int cl = (lane & 3) * 2;     // 0,2,4,6

#pragma unroll
    for (int mt = 0; mt < 4; ++mt) {
#pragma unroll
        for (int half = 0; half < 2; ++half) {
            const int rr = r_base + mt * 16 + rl + half * 8;
            const int l = rr % SEQL;
            const int tt = l / NPATCH;
            const int pp = l % NPATCH;
#pragma unroll
            for (int nt = 0; nt < 4; ++nt) {
                const int col = c_base + nt * 8 + cl;
                float v0 = acc[mt][nt][half * 2 + 0] + bias[col];
                float v1 = acc[mt][nt][half * 2 + 1] + bias[col + 1];
                if (epi == EPI_EMBED) {
                    v0 += sp[(size_t)pp * DIM + col]     + tp[(size_t)tt * DIM + col];
                    v1 += sp[(size_t)pp * DIM + col + 1] + tp[(size_t)tt * DIM + col + 1];
                } else if (epi == EPI_RES) {
                    v0 += res[(size_t)rr * N + col];
                    v1 += res[(size_t)rr * N + col + 1];
                } else if (epi == EPI_GELU) {
                    v0 = 0.5f * v0 * (1.0f + erff(v0 * 0.70710678118654752f));
                    v1 = 0.5f * v1 * (1.0f + erff(v1 * 0.70710678118654752f));
                }
                *(float2*)(C + (size_t)rr * N + col) = make_float2(v0, v1);
            }
        }
    }
}

// ---------------- LayerNorm: one block (128 thr) per row of 512 ----------------
__global__ void ln_kernel(const float* __restrict__ x, const float* __restrict__ g,
                          const float* __restrict__ b, float* __restrict__ y)
{
    const int row = blockIdx.x;
    const int tid = threadIdx.x;   // 128
    const float4 v = *(const float4*)(x + (size_t)row * DIM + tid * 4);

    __shared__ float red[4];
    float s = v.x + v.y + v.z + v.w;
#pragma unroll
    for (int o = 16; o > 0; o >>= 1) s += __shfl_xor_sync(0xffffffffu, s, o);
    if ((tid & 31) == 0) red[tid >> 5] = s;
    __syncthreads();
    const float mean = (red[0] + red[1] + red[2] + red[3]) * (1.0f / DIM);

    const float d0 = v.x - mean, d1 = v.y - mean, d2 = v.z - mean, d3 = v.w - mean;
    float q = d0 * d0 + d1 * d1 + d2 * d2 + d3 * d3;
    __syncthreads();
#pragma unroll
    for (int o = 16; o > 0; o >>= 1) q += __shfl_xor_sync(0xffffffffu, q, o);
    if ((tid & 31) == 0) red[tid >> 5] = q;
    __syncthreads();
    const float var = (red[0] + red[1] + red[2] + red[3]) * (1.0f / DIM);
    const float rs = rsqrtf(var + 1e-5f);

    const float4 gv = *(const float4*)(g + tid * 4);
    const float4 bv = *(const float4*)(b + tid * 4);
    float4 o4;
    o4.x = d0 * rs * gv.x + bv.x;
    o4.y = d1 * rs * gv.y + bv.y;
    o4.z = d2 * rs * gv.z + bv.z;
    o4.w = d3 * rs * gv.w + bv.w;
    *(float4*)(y + (size_t)row * DIM + tid * 4) = o4;
}

// ---------------- flash-style attention (unchanged) ----------------
#define AT   64
#define APAD 68
__global__ __launch_bounds__(256)
void attn_kernel(const float* __restrict__ qkv, const float* __restrict__ keep,
                 float* __restrict__ out)
{
    extern __shared__ float sm[];
    float* Qt   = sm;
    float* Kt   = Qt + AT * APAD;
    float* Vs   = Kt + AT * APAD;
    float* Ps   = Vs + AT * APAD;
    float* mrow = Ps + AT * APAD;
    float* lrow = mrow + AT;
    float* crow = lrow + AT;
    float* kqs  = crow + AT;
    float* kks  = kqs + AT;

    const int qt = blockIdx.x;
    const int h  = blockIdx.y;
    const int n  = blockIdx.z;
    const int tid = threadIdx.x;
    const int tx = tid & 15;
    const int ty = tid >> 4;
    const int tx4 = tx * 4, ty4 = ty * 4;
    const int q0 = qt * AT;

    const float* base = qkv + (size_t)n * SEQL * (3 * DIM);

#pragma unroll
    for (int it = 0; it < 4; ++it) {
        int idx = tid + it * 256;
        int row = idx >> 4;
        int cg  = (idx & 15) * 4;
        int qrow = q0 + row;
        int src = qrow < SEQL ? qrow : (SEQL - 1);
        float4 v = *(const float4*)(base + (size_t)src * (3 * DIM) + h * DH + cg);
        Qt[(cg + 0) * APAD + row] = v.x;
        Qt[(cg + 1) * APAD + row] = v.y;
        Qt[(cg + 2) * APAD + row] = v.z;
        Qt[(cg + 3) * APAD + row] = v.w;
    }
    if (tid < AT) {
        int qrow = q0 + tid;
        kqs[tid] = (qrow < SEQL) ? keep[(size_t)n * SEQL + qrow] : 0.f;
        mrow[tid] = -1e30f;
        lrow[tid] = 0.f;
    }
    float o[4][4];
#pragma unroll
    for (int i = 0; i < 4; ++i)
#pragma unroll
        for (int j = 0; j < 4; ++j) o[i][j] = 0.f;
    __syncthreads();

    float kqv[4];
#pragma unroll
    for (int i = 0; i < 4; ++i) kqv[i] = kqs[ty4 + i];

    for (int kt0 = 0; kt0 < SEQL; kt0 += AT) {
#pragma unroll
        for (int it = 0; it < 4; ++it) {
            int idx = tid + it * 256;
            int row = idx >> 4;
            int cg  = (idx & 15) * 4;
            int krow = kt0 + row;
            int src = krow < SEQL ? krow : (SEQL - 1);
            const float* kp = base + (size_t)src * (3 * DIM) + DIM + h * DH + cg;
            float4 k4 = *(const float4*)kp;
            Kt[(cg + 0) * APAD + row] = k4.x;
            Kt[(cg + 1) * APAD + row] = k4.y;
            Kt[(cg + 2) * APAD + row] = k4.z;
            Kt[(cg + 3) * APAD + row] = k4.w;
            const float* vp = base + (size_t)src * (3 * DIM) + 2 * DIM + h * DH + cg;
            float4 v4 = *(const float4*)vp;
            *(float4*)&Vs[row * APAD + cg] = v4;
        }
        if (tid < AT)
            kks[tid] = (kt0 + tid < SEQL) ? keep[(size_t)n * SEQL + kt0 + tid] : 0.f;
        __syncthreads();

        float s[4][4];
#pragma unroll
        for (int i = 0; i < 4; ++i)
#pragma unroll
            for (int j = 0; j < 4; ++j) s[i][j] = 0.f;
#pragma unroll 8
        for (int d = 0; d < DH; ++d) {
            float a[4], bb[4];
#pragma unroll
            for (int i = 0; i < 4; ++i) a[i] = Qt[d * APAD + ty4 + i];
#pragma unroll
            for (int j = 0; j < 4; ++j) bb[j] = Kt[d * APAD + tx4 + j];
#pragma unroll
            for (int i = 0; i < 4; ++i)
#pragma unroll
                for (int j = 0; j < 4; ++j)
                    s[i][j] = fmaf(a[i], bb[j], s[i][j]);
        }

#pragma unroll
        for (int i = 0; i < 4; ++i) {
#pragma unroll
            for (int j = 0; j < 4; ++j) {
                int kidx = kt0 + tx4 + j;
                float val;
                if (kidx >= SEQL) {
                    val = -1e30f;
                } else if (kqv[i] > 0.5f) {
                    val = (kks[tx4 + j] > 0.5f) ? s[i][j] * 0.125f : -1e30f;
                } else {
                    val = 0.f;
                }
                Ps[(ty4 + i) * APAD + tx4 + j] = val;
            }
        }
        __syncthreads();

        if (tid < AT) {
            float* pr = Ps + tid * APAD;
            float mo = mrow[tid];
            float tm = -1e30f;
#pragma unroll 8
            for (int k = 0; k < AT; ++k) tm = fmaxf(tm, pr[k]);
            float mn = fmaxf(mo, tm);
            float c = __expf(mo - mn);
            float srow = 0.f;
#pragma unroll 8
            for (int k = 0; k < AT; ++k) {
                float pv = pr[k];
                float e = (pv <= -1e29f) ? 0.f : __expf(pv - mn);
                pr[k] = e;
                srow += e;
            }
            lrow[tid] = lrow[tid] * c + srow;
            mrow[tid] = mn;
            crow[tid] = c;
        }
        __syncthreads();

        float ci[4];
#pragma unroll
        for (int i = 0; i < 4; ++i) ci[i] = crow[ty4 + i];
#pragma unroll
        for (int i = 0; i < 4; ++i)
#pragma unroll
            for (int j = 0; j < 4; ++j) o[i][j] *= ci[i];
#pragma unroll 8
        for (int k = 0; k < AT; ++k) {
            float p[4], vv[4];
#pragma unroll
            for (int i = 0; i < 4; ++i) p[i] = Ps[(ty4 + i) * APAD + k];
#pragma unroll
            for (int j = 0; j < 4; ++j) vv[j] = Vs[k * APAD + tx4 + j];
#pragma unroll
            for (int i = 0; i < 4; ++i)
#pragma unroll
                for (int j = 0; j < 4; ++j)
                    o[i][j] = fmaf(p[i], vv[j], o[i][j]);
        }
        __syncthreads();
    }

#pragma unroll
    for (int i = 0; i < 4; ++i) {
        int q = q0 + ty4 + i;
        if (q < SEQL) {
            float inv = 1.0f / lrow[ty4 + i];
#pragma unroll
            for (int j = 0; j < 4; ++j)
                out[((size_t)n * SEQL + q) * DIM + h * DH + tx4 + j] = o[i][j] * inv;
        }
    }
}

#define ATT_SMEM ((4 * AT * APAD + 5 * AT) * (int)sizeof(float))

// ---------------- orchestration ----------------
extern "C" void kernel_launch(void* const* d_in, const int* in_sizes, int n_in,
                              void* d_out, int out_size)
{
    (void)in_sizes; (void)n_in; (void)out_size;
    const float* patch    = (const float*)d_in[0];
    const int*   done     = (const int*)  d_in[1];
    const float* W_embed  = (const float*)d_in[2];
    const float* b_embed  = (const float*)d_in[3];
    const float* spatial  = (const float*)d_in[4];
    const float* temporal = (const float*)d_in[5];
    const float* ln1_g    = (const float*)d_in[6];
    const float* ln1_b    = (const float*)d_in[7];
    const float* Wqkv     = (const float*)d_in[8];
    const float* bqkv     = (const float*)d_in[9];
    const float* Wo       = (const float*)d_in[10];
    const float* bo       = (const float*)d_in[11];
    const float* ln2_g    = (const float*)d_in[12];
    const float* ln2_b    = (const float*)d_in[13];
    const float* W1       = (const float*)d_in[14];
    const float* b1       = (const float*)d_in[15];
    const float* W2       = (const float*)d_in[16];
    const float* b2       = (const float*)d_in[17];
    const float* out_g    = (const float*)d_in[18];
    const float* out_b    = (const float*)d_in[19];
    float* out = (float*)d_out;

    float *x, *h, *qkv, *att, *mlp, *keep, *wT;
    cudaGetSymbolAddress((void**)&x,    g_x);
    cudaGetSymbolAddress((void**)&h,    g_h);
    cudaGetSymbolAddress((void**)&qkv,  g_qkv);
    cudaGetSymbolAddress((void**)&att,  g_att);
    cudaGetSymbolAddress((void**)&mlp,  g_mlp);
    cudaGetSymbolAddress((void**)&keep, g_keep);
    cudaGetSymbolAddress((void**)&wT,   g_wT);

    cudaFuncSetAttribute(attn_kernel, cudaFuncAttributeMaxDynamicSharedMemorySize, ATT_SMEM);

    float* qkvT = wT + OFF_QKVT;
    float* woT  = wT + OFF_WOT;
    float* w1T  = wT + OFF_W1T;
    float* w2T  = wT + OFF_W2T;
    float* webT = wT + OFF_WEBT;

    // weight transposes ([K][N] -> [N][K])
    dim3 tb(32, 8);
    transpose_kernel<<<dim3(16, 14), tb>>>(W_embed, webT, PDIM, DIM);
    for (int i = 0; i < DEPTH; ++i) {
        transpose_kernel<<<dim3(48, 16), tb>>>(Wqkv + (size_t)i * DIM * 3 * DIM,
                                               qkvT + (size_t)i * 3 * DIM * DIM, DIM, 3 * DIM);
        transpose_kernel<<<dim3(16, 16), tb>>>(Wo + (size_t)i * DIM * DIM,
                                               woT + (size_t)i * DIM * DIM, DIM, DIM);
        transpose_kernel<<<dim3(64, 16), tb>>>(W1 + (size_t)i * DIM * MLPD,
                                               w1T + (size_t)i * DIM * MLPD, DIM, MLPD);
        transpose_kernel<<<dim3(16, 64), tb>>>(W2 + (size_t)i * MLPD * DIM,
                                               w2T + (size_t)i * MLPD * DIM, MLPD, DIM);
    }

    keep_kernel<<<1, 32>>>(done, keep);

    // patch embed + pos embed
    tgemm_kernel<<<dim3(DIM / 128, TOK / 128), 256>>>(
        patch, webT, b_embed, nullptr, x, TOK, DIM, PDIM, EPI_EMBED, spatial, temporal);

    for (int i = 0; i < DEPTH; ++i) {
        ln_kernel<<<TOK, 128>>>(x, ln1_g + (size_t)i * DIM, ln1_b + (size_t)i * DIM, h);

        tgemm_kernel<<<dim3(3 * DIM / 128, TOK / 128), 256>>>(
            h, qkvT + (size_t)i * 3 * DIM * DIM, bqkv + (size_t)i * 3 * DIM,
            nullptr, qkv, TOK, 3 * DIM, DIM, EPI_NONE, nullptr, nullptr);

        attn_kernel<<<dim3((SEQL + AT - 1) / AT, HEADS, NB), 256, ATT_SMEM>>>(qkv, keep, att);

        tgemm_kernel<<<dim3(DIM / 128, TOK / 128), 256>>>(
            att, woT + (size_t)i * DIM * DIM, bo + (size_t)i * DIM,
            x, x, TOK, DIM, DIM, EPI_RES, nullptr, nullptr);

        ln_kernel<<<TOK, 128>>>(x, ln2_g + (size_t)i * DIM, ln2_b + (size_t)i * DIM, h);

        tgemm_kernel<<<dim3(MLPD / 128, TOK / 128), 256>>>(
            h, w1T + (size_t)i * DIM * MLPD, b1 + (size_t)i * MLPD,
            nullptr, mlp, TOK, MLPD, DIM, EPI_GELU, nullptr, nullptr);

        tgemm_kernel<<<dim3(DIM / 128, TOK / 128), 256>>>(
            mlp, w2T + (size_t)i * MLPD * DIM, b2 + (size_t)i * DIM,
            x, x, TOK, DIM, MLPD, EPI_RES, nullptr, nullptr);
    }

    ln_kernel<<<TOK, 128>>>(x, out_g, out_b, out);
}

// round 5
// speedup vs baseline: 3.8982x; 1.9273x over previous
#include <cuda_runtime.h>
#include <cstdint>
#include <cstddef>

// ---------------- problem constants ----------------
#define NB      32
#define T_STEP  16
#define NPATCH  49
#define SEQL    784            // T_STEP * NUM_PATCHES
#define TOK     25088          // NB * SEQL
#define DIM     512
#define HEADS   8
#define DH      64
#define MLPD    2048
#define PDIM    432
#define DEPTH   4

// ---------------- scratch (device globals; no allocations allowed) ----------------
__device__ float g_x  [(size_t)TOK * DIM];
__device__ float g_h  [(size_t)TOK * DIM];
__device__ float g_qkv[(size_t)TOK * 3 * DIM];
__device__ float g_att[(size_t)TOK * DIM];
__device__ float g_mlp[(size_t)TOK * MLPD];
__device__ int   g_s0 [NB];
__device__ float g_pm [(size_t)NB * 8 * DIM];

// transposed weights  [N][K] layouts
#define OFF_QKVT 0
#define OFF_WOT  3145728
#define OFF_W1T  4194304
#define OFF_W2T  8388608
#define OFF_WEBT 12582912
__device__ float g_wT[12804096];

// ---------------- epilogue modes ----------------
#define EPI_NONE  0
#define EPI_EMBED 1
#define EPI_RES   2
#define EPI_GELU  3

// ---------------- helpers ----------------
__device__ __forceinline__ uint32_t smem_u32(const void* p) {
    uint32_t a;
    asm("{ .reg .u64 t; cvta.to.shared.u64 t, %1; cvt.u32.u64 %0, t; }" : "=r"(a) : "l"(p));
    return a;
}

__device__ __forceinline__ uint32_t f2tf32(float x) {
    uint32_t u;
    asm("cvt.rna.tf32.f32 %0, %1;" : "=r"(u) : "f"(x));
    return u;
}

__device__ __forceinline__ void mma_tf32(float c[4], const uint32_t a[4], const uint32_t b[2]) {
    asm volatile(
        "mma.sync.aligned.m16n8k8.row.col.f32.tf32.tf32.f32 "
        "{%0,%1,%2,%3}, {%4,%5,%6,%7}, {%8,%9}, {%0,%1,%2,%3};\n"
        : "+f"(c[0]), "+f"(c[1]), "+f"(c[2]), "+f"(c[3])
        : "r"(a[0]), "r"(a[1]), "r"(a[2]), "r"(a[3]), "r"(b[0]), "r"(b[1]));
}

__device__ __forceinline__ void ldsm_x4(uint32_t& r0, uint32_t& r1, uint32_t& r2,
                                        uint32_t& r3, uint32_t addr) {
    asm volatile("ldmatrix.sync.aligned.m8n8.x4.shared.b16 {%0,%1,%2,%3}, [%4];"
                 : "=r"(r0), "=r"(r1), "=r"(r2), "=r"(r3) : "r"(addr));
}

// swizzled 16B-unit offset within an operand tile: rows of 16 tf32 (4 x 16B units)
__device__ __forceinline__ uint32_t swz16(int m, int q) {
    return (uint32_t)(m * 4 + (q ^ ((m >> 1) & 3)));
}

// ---------------- episodic mask suffix start: s0[n] ----------------
__global__ void s0_kernel(const int* __restrict__ done, int* __restrict__ s0)
{
    int n = threadIdx.x;
    if (n >= NB) return;
    int last = -1;
    for (int t = 0; t < T_STEP - 1; ++t)
        if (done[n * (T_STEP - 1) + t]) last = t;
    s0[n] = (last + 1) * NPATCH;   // first kept token; 0 => nothing masked
}

// ---------------- partial V sums: pm[n][part][d] = sum over 98 rows ----------------
__global__ void pmean_kernel(const float* __restrict__ qkv, float* __restrict__ pm)
{
    const int part = blockIdx.x;   // 0..7
    const int n = blockIdx.y;
    const int d = threadIdx.x;     // 512
    const float* base = qkv + (size_t)n * SEQL * (3 * DIM) + 2 * DIM + d;
    const int r0 = part * 98;
    float s = 0.f;
#pragma unroll 7
    for (int r = 0; r < 98; ++r)
        s += base[(size_t)(r0 + r) * (3 * DIM)];
    pm[((size_t)n * 8 + part) * DIM + d] = s;
}

// ---------------- fill masked-query rows with mean(V) ----------------
__global__ void fill_kernel(const float* __restrict__ pm, const int* __restrict__ s0,
                            float* __restrict__ out)
{
    const int q = blockIdx.x;
    const int n = blockIdx.y;
    if (q >= s0[n]) return;
    const int d = threadIdx.x;   // 512
    float s = 0.f;
#pragma unroll
    for (int p = 0; p < 8; ++p)
        s += pm[((size_t)n * 8 + p) * DIM + d];
    out[((size_t)n * SEQL + q) * DIM + d] = s * (1.0f / 784.0f);
}

// ---------------- weight transpose: src[K][N] -> dst[N][K] ----------------
__global__ void transpose_kernel(const float* __restrict__ src, float* __restrict__ dst,
                                 int K, int N)
{
    __shared__ float t[32][33];
    int x = blockIdx.x * 32 + threadIdx.x;   // n
    int y = blockIdx.y * 32 + threadIdx.y;   // k
#pragma unroll
    for (int j = 0; j < 32; j += 8)
        if (x < N && y + j < K)
            t[threadIdx.y + j][threadIdx.x] = src[(size_t)(y + j) * N + x];
    __syncthreads();
    x = blockIdx.y * 32 + threadIdx.x;       // k
    y = blockIdx.x * 32 + threadIdx.y;       // n
#pragma unroll
    for (int j = 0; j < 32; j += 8)
        if (x < K && y + j < N)
            dst[(size_t)(y + j) * K + x] = t[threadIdx.x][threadIdx.y + j];
}

// ---------------- tf32 mma.sync GEMM with ldmatrix (round-4 design) ----------
__global__ __launch_bounds__(256, 2)
void tgemm_kernel(const float* __restrict__ A, const float* __restrict__ Bt,
                  const float* __restrict__ bias, const float* __restrict__ res,
                  float* __restrict__ C, int M, int N, int K, int epi,
                  const float* __restrict__ sp, const float* __restrict__ tp)
{
    __shared__ uint32_t As[2048];   // 128 rows x 16 tf32
    __shared__ uint32_t Bs[2048];

    const int tid = threadIdx.x;
    const int lane = tid & 31;
    const int wid = tid >> 5;
    const int warp_m = wid >> 2;    // 0..1
    const int warp_n = wid & 3;     // 0..3
    const int n0 = blockIdx.x * 128;
    const int m0 = blockIdx.y * 128;

    const int l_m = tid >> 2;        // 0..63
    const int l_q = tid & 3;         // 16B unit within row

    const uint32_t sA = smem_u32(As);
    const uint32_t sB = smem_u32(Bs);
    const uint32_t stsA0 = sA + swz16(l_m, l_q) * 16;
    const uint32_t stsA1 = sA + swz16(l_m + 64, l_q) * 16;
    const uint32_t stsB0 = sB + swz16(l_m, l_q) * 16;
    const uint32_t stsB1 = sB + swz16(l_m + 64, l_q) * 16;

    const float* Ap0 = A + (size_t)(m0 + l_m) * K + l_q * 4;
    const float* Ap1 = A + (size_t)(m0 + l_m + 64) * K + l_q * 4;
    const float* Bp0 = Bt + (size_t)(n0 + l_m) * K + l_q * 4;
    const float* Bp1 = Bt + (size_t)(n0 + l_m + 64) * K + l_q * 4;

    const int g = lane >> 3;
    const int r = lane & 7;
    const int a_mrow0 = warp_m * 64 + (g & 1) * 8 + r;
    const int a_kq = g >> 1;
    const int b_nrow0 = warp_n * 32 + (g >> 1) * 8 + r;
    const int b_kq = g & 1;

    float acc[4][4][4];
#pragma unroll
    for (int mt = 0; mt < 4; ++mt)
#pragma unroll
        for (int nt = 0; nt < 4; ++nt)
#pragma unroll
            for (int e = 0; e < 4; ++e) acc[mt][nt][e] = 0.f;

    const int niter = K >> 4;

    float4 ra0, ra1, rb0, rb1;
    ra0 = *(const float4*)Ap0;
    ra1 = *(const float4*)Ap1;
    rb0 = *(const float4*)Bp0;
    rb1 = *(const float4*)Bp1;

    for (int i = 0; i < niter; ++i) {
        uint4 u;
        u.x = f2tf32(ra0.x); u.y = f2tf32(ra0.y); u.z = f2tf32(ra0.z); u.w = f2tf32(ra0.w);
        *(uint4*)(As + (stsA0 - sA) / 4) = u;
        u.x = f2tf32(ra1.x); u.y = f2tf32(ra1.y); u.z = f2tf32(ra1.z); u.w = f2tf32(ra1.w);
        *(uint4*)(As + (stsA1 - sA) / 4) = u;
        u.x = f2tf32(rb0.x); u.y = f2tf32(rb0.y); u.z = f2tf32(rb0.z); u.w = f2tf32(rb0.w);
        *(uint4*)(Bs + (stsB0 - sB) / 4) = u;
        u.x = f2tf32(rb1.x); u.y = f2tf32(rb1.y); u.z = f2tf32(rb1.z); u.w = f2tf32(rb1.w);
        *(uint4*)(Bs + (stsB1 - sB) / 4) = u;
        __syncthreads();

        if (i + 1 < niter) {
            const int ko = (i + 1) * 16;
            ra0 = *(const float4*)(Ap0 + ko);
            ra1 = *(const float4*)(Ap1 + ko);
            rb0 = *(const float4*)(Bp0 + ko);
            rb1 = *(const float4*)(Bp1 + ko);
        }

#pragma unroll
        for (int ks = 0; ks < 2; ++ks) {
            uint32_t af[4][4];
            uint32_t bf[4][2];
#pragma unroll
            for (int mt = 0; mt < 4; ++mt) {
                const int mrow = a_mrow0 + mt * 16;
                const uint32_t addr = sA + swz16(mrow, ks * 2 + a_kq) * 16;
                ldsm_x4(af[mt][0], af[mt][1], af[mt][2], af[mt][3], addr);
            }
#pragma unroll
            for (int p = 0; p < 2; ++p) {
                const int nrow = b_nrow0 + p * 16;
                const uint32_t addr = sB + swz16(nrow, ks * 2 + b_kq) * 16;
                ldsm_x4(bf[p * 2][0], bf[p * 2][1], bf[p * 2 + 1][0], bf[p * 2 + 1][1], addr);
            }
#pragma unroll
            for (int mt = 0; mt < 4; ++mt)
#pragma unroll
                for (int nt = 0; nt < 4; ++nt)
                    mma_tf32(acc[mt][nt], af[mt], bf[nt]);
        }
        __syncthreads();
    }

    const int r_base = m0 + warp_m * 64;
    const int c_base = n0 + warp_n * 32;
    const int rl = lane >> 2;
    const int cl = (lane & 3) * 2;

#pragma unroll
    for (int mt = 0; mt < 4; ++mt) {
#pragma unroll
        for (int half = 0; half < 2; ++half) {
            const int rr = r_base + mt * 16 + rl + half * 8;
            const int l = rr % SEQL;
            const int tt = l / NPATCH;
            const int pp = l % NPATCH;
#pragma unroll
            for (int nt = 0; nt < 4; ++nt) {
                const int col = c_base + nt * 8 + cl;
                float v0 = acc[mt][nt][half * 2 + 0] + bias[col];
                float v1 = acc[mt][nt][half * 2 + 1] + bias[col + 1];
                if (epi == EPI_EMBED) {
                    v0 += sp[(size_t)pp * DIM + col]     + tp[(size_t)tt * DIM + col];
                    v1 += sp[(size_t)pp * DIM + col + 1] + tp[(size_t)tt * DIM + col + 1];
                } else if (epi == EPI_RES) {
                    v0 += res[(size_t)rr * N + col];
                    v1 += res[(size_t)rr * N + col + 1];
                } else if (epi == EPI_GELU) {
                    v0 = 0.5f * v0 * (1.0f + erff(v0 * 0.70710678118654752f));
                    v1 = 0.5f * v1 * (1.0f + erff(v1 * 0.70710678118654752f));
                }
                *(float2*)(C + (size_t)rr * N + col) = make_float2(v0, v1);
            }
        }
    }
}

// ---------------- LayerNorm: one block (128 thr) per row of 512 ----------------
__global__ void ln_kernel(const float* __restrict__ x, const float* __restrict__ g,
                          const float* __restrict__ b, float* __restrict__ y)
{
    const int row = blockIdx.x;
    const int tid = threadIdx.x;   // 128
    const float4 v = *(const float4*)(x + (size_t)row * DIM + tid * 4);

    __shared__ float red[4];
    float s = v.x + v.y + v.z + v.w;
#pragma unroll
    for (int o = 16; o > 0; o >>= 1) s += __shfl_xor_sync(0xffffffffu, s, o);
    if ((tid & 31) == 0) red[tid >> 5] = s;
    __syncthreads();
    const float mean = (red[0] + red[1] + red[2] + red[3]) * (1.0f / DIM);

    const float d0 = v.x - mean, d1 = v.y - mean, d2 = v.z - mean, d3 = v.w - mean;
    float q = d0 * d0 + d1 * d1 + d2 * d2 + d3 * d3;
    __syncthreads();
#pragma unroll
    for (int o = 16; o > 0; o >>= 1) q += __shfl_xor_sync(0xffffffffu, q, o);
    if ((tid & 31) == 0) red[tid >> 5] = q;
    __syncthreads();
    const float var = (red[0] + red[1] + red[2] + red[3]) * (1.0f / DIM);
    const float rs = rsqrtf(var + 1e-5f);

    const float4 gv = *(const float4*)(g + tid * 4);
    const float4 bv = *(const float4*)(b + tid * 4);
    float4 o4;
    o4.x = d0 * rs * gv.x + bv.x;
    o4.y = d1 * rs * gv.y + bv.y;
    o4.z = d2 * rs * gv.z + bv.z;
    o4.w = d3 * rs * gv.w + bv.w;
    *(float4*)(y + (size_t)row * DIM + tid * 4) = o4;
}

// ---------------- flash attention over the kept suffix only ----------------
// Masked queries (q < s0) are written by fill_kernel (exact uniform-softmax = meanV).
// Kept queries attend only to keys k >= s0.
#define AT   64
#define APAD 68
__global__ __launch_bounds__(256)
void attn_kernel(const float* __restrict__ qkv, const int* __restrict__ s0arr,
                 float* __restrict__ out)
{
    const int qt = blockIdx.x;
    const int h  = blockIdx.y;
    const int n  = blockIdx.z;
    const int q0 = qt * AT;
    const int s0n = s0arr[n];
    if (q0 + AT <= s0n) return;          // tile fully masked -> fill_kernel covers it

    extern __shared__ float sm[];
    float* Qt   = sm;
    float* Kt   = Qt + AT * APAD;
    float* Vs   = Kt + AT * APAD;
    float* Ps   = Vs + AT * APAD;
    float* mrow = Ps + AT * APAD;
    float* lrow = mrow + AT;
    float* crow = lrow + AT;

    const int tid = threadIdx.x;
    const int tx = tid & 15;
    const int ty = tid >> 4;
    const int tx4 = tx * 4, ty4 = ty * 4;

    const float* base = qkv + (size_t)n * SEQL * (3 * DIM);

#pragma unroll
    for (int it = 0; it < 4; ++it) {
        int idx = tid + it * 256;
        int row = idx >> 4;
        int cg  = (idx & 15) * 4;
        int qrow = q0 + row;
        int src = qrow < SEQL ? qrow : (SEQL - 1);
        float4 v = *(const float4*)(base + (size_t)src * (3 * DIM) + h * DH + cg);
        Qt[(cg + 0) * APAD + row] = v.x;
        Qt[(cg + 1) * APAD + row] = v.y;
        Qt[(cg + 2) * APAD + row] = v.z;
        Qt[(cg + 3) * APAD + row] = v.w;
    }
    if (tid < AT) {
        mrow[tid] = -1e30f;
        lrow[tid] = 0.f;
    }
    float o[4][4];
#pragma unroll
    for (int i = 0; i < 4; ++i)
#pragma unroll
        for (int j = 0; j < 4; ++j) o[i][j] = 0.f;
    __syncthreads();

    const int ktstart = (s0n / AT) * AT;   // first kv tile containing kept keys

    for (int kt0 = ktstart; kt0 < SEQL; kt0 += AT) {
#pragma unroll
        for (int it = 0; it < 4; ++it) {
            int idx = tid + it * 256;
            int row = idx >> 4;
            int cg  = (idx & 15) * 4;
            int krow = kt0 + row;
            int src = krow < SEQL ? krow : (SEQL - 1);
            const float* kp = base + (size_t)src * (3 * DIM) + DIM + h * DH + cg;
            float4 k4 = *(const float4*)kp;
            Kt[(cg + 0) * APAD + row] = k4.x;
            Kt[(cg + 1) * APAD + row] = k4.y;
            Kt[(cg + 2) * APAD + row] = k4.z;
            Kt[(cg + 3) * APAD + row] = k4.w;
            const float* vp = base + (size_t)src * (3 * DIM) + 2 * DIM + h * DH + cg;
            float4 v4 = *(const float4*)vp;
            *(float4*)&Vs[row * APAD + cg] = v4;
        }
        __syncthreads();

        float s[4][4];
#pragma unroll
        for (int i = 0; i < 4; ++i)
#pragma unroll
            for (int j = 0; j < 4; ++j) s[i][j] = 0.f;
#pragma unroll 8
        for (int d = 0; d < DH; ++d) {
            float a[4], bb[4];
#pragma unroll
            for (int i = 0; i < 4; ++i) a[i] = Qt[d * APAD + ty4 + i];
#pragma unroll
            for (int j = 0; j < 4; ++j) bb[j] = Kt[d * APAD + tx4 + j];
#pragma unroll
            for (int i = 0; i < 4; ++i)
#pragma unroll
                for (int j = 0; j < 4; ++j)
                    s[i][j] = fmaf(a[i], bb[j], s[i][j]);
        }

#pragma unroll
        for (int i = 0; i < 4; ++i) {
#pragma unroll
            for (int j = 0; j < 4; ++j) {
                const int kidx = kt0 + tx4 + j;
                const float val = (kidx >= s0n && kidx < SEQL) ? s[i][j] * 0.125f : -1e30f;
                Ps[(ty4 + i) * APAD + tx4 + j] = val;
            }
        }
        __syncthreads();

        if (tid < AT) {
            float* pr = Ps + tid * APAD;
            float mo = mrow[tid];
            float tm = -1e30f;
#pragma unroll 8
            for (int k = 0; k < AT; ++k) tm = fmaxf(tm, pr[k]);
            float mn = fmaxf(mo, tm);
            float c = __expf(mo - mn);
            float srow = 0.f;
#pragma unroll 8
            for (int k = 0; k < AT; ++k) {
                float pv = pr[k];
                float e = (pv <= -1e29f) ? 0.f : __expf(pv - mn);
                pr[k] = e;
                srow += e;
            }
            lrow[tid] = lrow[tid] * c + srow;
            mrow[tid] = mn;
            crow[tid] = c;
        }
        __syncthreads();

        float ci[4];
#pragma unroll
        for (int i = 0; i < 4; ++i) ci[i] = crow[ty4 + i];
#pragma unroll
        for (int i = 0; i < 4; ++i)
#pragma unroll
            for (int j = 0; j < 4; ++j) o[i][j] *= ci[i];
#pragma unroll 8
        for (int k = 0; k < AT; ++k) {
            float p[4], vv[4];
#pragma unroll
            for (int i = 0; i < 4; ++i) p[i] = Ps[(ty4 + i) * APAD + k];
#pragma unroll
            for (int j = 0; j < 4; ++j) vv[j] = Vs[k * APAD + tx4 + j];
#pragma unroll
            for (int i = 0; i < 4; ++i)
#pragma unroll
                for (int j = 0; j < 4; ++j)
                    o[i][j] = fmaf(p[i], vv[j], o[i][j]);
        }
        __syncthreads();
    }

    // write only kept query rows; fill_kernel owns the masked ones
#pragma unroll
    for (int i = 0; i < 4; ++i) {
        const int q = q0 + ty4 + i;
        if (q < SEQL && q >= s0n) {
            const float inv = 1.0f / lrow[ty4 + i];
#pragma unroll
            for (int j = 0; j < 4; ++j)
                out[((size_t)n * SEQL + q) * DIM + h * DH + tx4 + j] = o[i][j] * inv;
        }
    }
}

#define ATT_SMEM ((4 * AT * APAD + 3 * AT) * (int)sizeof(float))

// ---------------- orchestration ----------------
extern "C" void kernel_launch(void* const* d_in, const int* in_sizes, int n_in,
                              void* d_out, int out_size)
{
    (void)in_sizes; (void)n_in; (void)out_size;
    const float* patch    = (const float*)d_in[0];
    const int*   done     = (const int*)  d_in[1];
    const float* W_embed  = (const float*)d_in[2];
    const float* b_embed  = (const float*)d_in[3];
    const float* spatial  = (const float*)d_in[4];
    const float* temporal = (const float*)d_in[5];
    const float* ln1_g    = (const float*)d_in[6];
    const float* ln1_b    = (const float*)d_in[7];
    const float* Wqkv     = (const float*)d_in[8];
    const float* bqkv     = (const float*)d_in[9];
    const float* Wo       = (const float*)d_in[10];
    const float* bo       = (const float*)d_in[11];
    const float* ln2_g    = (const float*)d_in[12];
    const float* ln2_b    = (const float*)d_in[13];
    const float* W1       = (const float*)d_in[14];
    const float* b1       = (const float*)d_in[15];
    const float* W2       = (const float*)d_in[16];
    const float* b2       = (const float*)d_in[17];
    const float* out_g    = (const float*)d_in[18];
    const float* out_b    = (const float*)d_in[19];
    float* out = (float*)d_out;

    float *x, *h, *qkv, *att, *mlp, *pm, *wT;
    int* s0;
    cudaGetSymbolAddress((void**)&x,    g_x);
    cudaGetSymbolAddress((void**)&h,    g_h);
    cudaGetSymbolAddress((void**)&qkv,  g_qkv);
    cudaGetSymbolAddress((void**)&att,  g_att);
    cudaGetSymbolAddress((void**)&mlp,  g_mlp);
    cudaGetSymbolAddress((void**)&pm,   g_pm);
    cudaGetSymbolAddress((void**)&s0,   g_s0);
    cudaGetSymbolAddress((void**)&wT,   g_wT);

    cudaFuncSetAttribute(attn_kernel, cudaFuncAttributeMaxDynamicSharedMemorySize, ATT_SMEM);

    float* qkvT = wT + OFF_QKVT;
    float* woT  = wT + OFF_WOT;
    float* w1T  = wT + OFF_W1T;
    float* w2T  = wT + OFF_W2T;
    float* webT = wT + OFF_WEBT;

    // weight transposes ([K][N] -> [N][K])
    dim3 tb(32, 8);
    transpose_kernel<<<dim3(16, 14), tb>>>(W_embed, webT, PDIM, DIM);
    for (int i = 0; i < DEPTH; ++i) {
        transpose_kernel<<<dim3(48, 16), tb>>>(Wqkv + (size_t)i * DIM * 3 * DIM,
                                               qkvT + (size_t)i * 3 * DIM * DIM, DIM, 3 * DIM);
        transpose_kernel<<<dim3(16, 16), tb>>>(Wo + (size_t)i * DIM * DIM,
                                               woT + (size_t)i * DIM * DIM, DIM, DIM);
        transpose_kernel<<<dim3(64, 16), tb>>>(W1 + (size_t)i * DIM * MLPD,
                                               w1T + (size_t)i * DIM * MLPD, DIM, MLPD);
        transpose_kernel<<<dim3(16, 64), tb>>>(W2 + (size_t)i * MLPD * DIM,
                                               w2T + (size_t)i * MLPD * DIM, MLPD, DIM);
    }

    s0_kernel<<<1, 32>>>(done, s0);

    // patch embed + pos embed
    tgemm_kernel<<<dim3(DIM / 128, TOK / 128), 256>>>(
        patch, webT, b_embed, nullptr, x, TOK, DIM, PDIM, EPI_EMBED, spatial, temporal);

    for (int i = 0; i < DEPTH; ++i) {
        ln_kernel<<<TOK, 128>>>(x, ln1_g + (size_t)i * DIM, ln1_b + (size_t)i * DIM, h);

        tgemm_kernel<<<dim3(3 * DIM / 128, TOK / 128), 256>>>(
            h, qkvT + (size_t)i * 3 * DIM * DIM, bqkv + (size_t)i * 3 * DIM,
            nullptr, qkv, TOK, 3 * DIM, DIM, EPI_NONE, nullptr, nullptr);

        pmean_kernel<<<dim3(8, NB), 512>>>(qkv, pm);
        fill_kernel<<<dim3(SEQL, NB), 512>>>(pm, s0, att);
        attn_kernel<<<dim3((SEQL + AT - 1) / AT, HEADS, NB), 256, ATT_SMEM>>>(qkv, s0, att);

        tgemm_kernel<<<dim3(DIM / 128, TOK / 128), 256>>>(
            att, woT + (size_t)i * DIM * DIM, bo + (size_t)i * DIM,
            x, x, TOK, DIM, DIM, EPI_RES, nullptr, nullptr);

        ln_kernel<<<TOK, 128>>>(x, ln2_g + (size_t)i * DIM, ln2_b + (size_t)i * DIM, h);

        tgemm_kernel<<<dim3(MLPD / 128, TOK / 128), 256>>>(
            h, w1T + (size_t)i * DIM * MLPD, b1 + (size_t)i * MLPD,
            nullptr, mlp, TOK, MLPD, DIM, EPI_GELU, nullptr, nullptr);

        tgemm_kernel<<<dim3(DIM / 128, TOK / 128), 256>>>(
            mlp, w2T + (size_t)i * MLPD * DIM, b2 + (size_t)i * DIM,
            x, x, TOK, DIM, MLPD, EPI_RES, nullptr, nullptr);
    }

    ln_kernel<<<TOK, 128>>>(x, out_g, out_b, out);
}

// round 6
// speedup vs baseline: 4.8866x; 1.2536x over previous
#include <cuda_runtime.h>
#include <cstdint>
#include <cstddef>

// ---------------- problem constants ----------------
#define NB      32
#define T_STEP  16
#define NPATCH  49
#define SEQL    784            // T_STEP * NUM_PATCHES
#define TOK     25088          // NB * SEQL
#define DIM     512
#define HEADS   8
#define DH      64
#define MLPD    2048
#define PDIM    432
#define DEPTH   4

// ---------------- scratch (device globals; no allocations allowed) ----------------
__device__ float g_x  [(size_t)TOK * DIM];
__device__ float g_h  [(size_t)TOK * DIM];
__device__ float g_qkv[(size_t)TOK * 3 * DIM];
__device__ float g_att[(size_t)TOK * DIM];
__device__ float g_mlp[(size_t)TOK * MLPD];
__device__ int   g_s0 [NB];
__device__ float g_pm [(size_t)NB * 8 * DIM];

// transposed weights  [N][K] layouts
#define OFF_QKVT 0
#define OFF_WOT  3145728
#define OFF_W1T  4194304
#define OFF_W2T  8388608
#define OFF_WEBT 12582912
__device__ float g_wT[12804096];

// ---------------- epilogue modes ----------------
#define EPI_NONE  0
#define EPI_EMBED 1
#define EPI_RES   2
#define EPI_GELU  3

// ---------------- helpers ----------------
__device__ __forceinline__ uint32_t smem_u32(const void* p) {
    uint32_t a;
    asm("{ .reg .u64 t; cvta.to.shared.u64 t, %1; cvt.u32.u64 %0, t; }" : "=r"(a) : "l"(p));
    return a;
}

__device__ __forceinline__ void mma_tf32(float c[4], const uint32_t a[4], const uint32_t b[2]) {
    asm volatile(
        "mma.sync.aligned.m16n8k8.row.col.f32.tf32.tf32.f32 "
        "{%0,%1,%2,%3}, {%4,%5,%6,%7}, {%8,%9}, {%0,%1,%2,%3};\n"
        : "+f"(c[0]), "+f"(c[1]), "+f"(c[2]), "+f"(c[3])
        : "r"(a[0]), "r"(a[1]), "r"(a[2]), "r"(a[3]), "r"(b[0]), "r"(b[1]));
}

__device__ __forceinline__ void ldsm_x4(uint32_t& r0, uint32_t& r1, uint32_t& r2,
                                        uint32_t& r3, uint32_t addr) {
    asm volatile("ldmatrix.sync.aligned.m8n8.x4.shared.b16 {%0,%1,%2,%3}, [%4];"
                 : "=r"(r0), "=r"(r1), "=r"(r2), "=r"(r3) : "r"(addr));
}

#define CP_ASYNC16(dst, src) \
    asm volatile("cp.async.cg.shared.global [%0], [%1], 16;" :: "r"(dst), "l"(src))
#define CP_COMMIT() asm volatile("cp.async.commit_group;" ::: "memory")
#define CP_WAIT1()  asm volatile("cp.async.wait_group 1;" ::: "memory")

// swizzled 16B-unit offset within an operand tile: rows of 16 tf32 (4 x 16B units)
__device__ __forceinline__ uint32_t swz16(int m, int q) {
    return (uint32_t)(m * 4 + (q ^ ((m >> 1) & 3)));
}

// ---------------- episodic mask suffix start: s0[n] ----------------
__global__ void s0_kernel(const int* __restrict__ done, int* __restrict__ s0)
{
    int n = threadIdx.x;
    if (n >= NB) return;
    int last = -1;
    for (int t = 0; t < T_STEP - 1; ++t)
        if (done[n * (T_STEP - 1) + t]) last = t;
    s0[n] = (last + 1) * NPATCH;
}

// ---------------- partial V sums ----------------
__global__ void pmean_kernel(const float* __restrict__ qkv, float* __restrict__ pm)
{
    const int part = blockIdx.x;   // 0..7
    const int n = blockIdx.y;
    const int d = threadIdx.x;     // 512
    const float* base = qkv + (size_t)n * SEQL * (3 * DIM) + 2 * DIM + d;
    const int r0 = part * 98;
    float s = 0.f;
#pragma unroll 7
    for (int r = 0; r < 98; ++r)
        s += base[(size_t)(r0 + r) * (3 * DIM)];
    pm[((size_t)n * 8 + part) * DIM + d] = s;
}

// ---------------- fill masked-query rows with mean(V) ----------------
__global__ void fill_kernel(const float* __restrict__ pm, const int* __restrict__ s0,
                            float* __restrict__ out)
{
    const int q = blockIdx.x;
    const int n = blockIdx.y;
    if (q >= s0[n]) return;
    const int d = threadIdx.x;   // 512
    float s = 0.f;
#pragma unroll
    for (int p = 0; p < 8; ++p)
        s += pm[((size_t)n * 8 + p) * DIM + d];
    out[((size_t)n * SEQL + q) * DIM + d] = s * (1.0f / 784.0f);
}

// ---------------- weight transpose (batched over z): src[K][N] -> dst[N][K] ----------
__global__ void transpose_kernel(const float* __restrict__ src0, float* __restrict__ dst0,
                                 int K, int N)
{
    const size_t zoff = (size_t)blockIdx.z * K * N;
    const float* src = src0 + zoff;
    float* dst = dst0 + zoff;
    __shared__ float t[32][33];
    int x = blockIdx.x * 32 + threadIdx.x;   // n
    int y = blockIdx.y * 32 + threadIdx.y;   // k
#pragma unroll
    for (int j = 0; j < 32; j += 8)
        if (x < N && y + j < K)
            t[threadIdx.y + j][threadIdx.x] = src[(size_t)(y + j) * N + x];
    __syncthreads();
    x = blockIdx.y * 32 + threadIdx.x;       // k
    y = blockIdx.x * 32 + threadIdx.y;       // n
#pragma unroll
    for (int j = 0; j < 32; j += 8)
        if (x < K && y + j < N)
            dst[(size_t)(y + j) * K + x] = t[threadIdx.x][threadIdx.y + j];
}

// ---------------- tf32 mma.sync GEMM, cp.async 3-stage pipeline ----------
// 128x128 CTA tile, BK=16, 256 threads, warp grid 2(m) x 4(n), warp tile 64x32.
// smem: 3 stages x (A 8KB + B 8KB) = 48KB dynamic. Raw fp32 bits fed to tf32 MMA.
#define GSTAGE 16384u
#define TG_SMEM (3 * 16384)
__global__ __launch_bounds__(256, 2)
void tgemm_kernel(const float* __restrict__ A, const float* __restrict__ Bt,
                  const float* __restrict__ bias, const float* __restrict__ res,
                  float* __restrict__ C, int M, int N, int K, int epi,
                  const float* __restrict__ sp, const float* __restrict__ tp)
{
    extern __shared__ __align__(16) uint8_t smraw[];

    const int tid = threadIdx.x;
    const int lane = tid & 31;
    const int wid = tid >> 5;
    const int warp_m = wid >> 2;    // 0..1
    const int warp_n = wid & 3;     // 0..3
    const int n0 = blockIdx.x * 128;
    const int m0 = blockIdx.y * 128;

    const int l_m = tid >> 2;        // 0..63
    const int l_q = tid & 3;

    const uint32_t sbase = smem_u32(smraw);
    const uint32_t dA0 = sbase + swz16(l_m, l_q) * 16;
    const uint32_t dA1 = sbase + swz16(l_m + 64, l_q) * 16;
    const uint32_t dB0 = dA0 + 8192u;
    const uint32_t dB1 = dA1 + 8192u;

    const float* Ap0 = A + (size_t)(m0 + l_m) * K + l_q * 4;
    const float* Ap1 = A + (size_t)(m0 + l_m + 64) * K + l_q * 4;
    const float* Bp0 = Bt + (size_t)(n0 + l_m) * K + l_q * 4;
    const float* Bp1 = Bt + (size_t)(n0 + l_m + 64) * K + l_q * 4;

    const int g = lane >> 3;
    const int r = lane & 7;
    const int a_mrow0 = warp_m * 64 + (g & 1) * 8 + r;
    const int a_kq = g >> 1;
    const int b_nrow0 = warp_n * 32 + (g >> 1) * 8 + r;
    const int b_kq = g & 1;

    float acc[4][4][4];
#pragma unroll
    for (int mt = 0; mt < 4; ++mt)
#pragma unroll
        for (int nt = 0; nt < 4; ++nt)
#pragma unroll
            for (int e = 0; e < 4; ++e) acc[mt][nt][e] = 0.f;

    const int niter = K >> 4;

    // prologue: issue stages 0 and 1
    {
        CP_ASYNC16(dA0, Ap0);
        CP_ASYNC16(dA1, Ap1);
        CP_ASYNC16(dB0, Bp0);
        CP_ASYNC16(dB1, Bp1);
        CP_COMMIT();
        CP_ASYNC16(dA0 + GSTAGE, Ap0 + 16);
        CP_ASYNC16(dA1 + GSTAGE, Ap1 + 16);
        CP_ASYNC16(dB0 + GSTAGE, Bp0 + 16);
        CP_ASYNC16(dB1 + GSTAGE, Bp1 + 16);
        CP_COMMIT();
    }

    int st = 0;                 // stage of iteration i
    for (int i = 0; i < niter; ++i) {
        CP_WAIT1();
        __syncthreads();

        // issue stage i+2 (overwrites stage computed at i-1; safe after the barrier)
        if (i + 2 < niter) {
            const int ko = (i + 2) * 16;
            const uint32_t so = (uint32_t)((st + 2) % 3) * GSTAGE;
            CP_ASYNC16(dA0 + so, Ap0 + ko);
            CP_ASYNC16(dA1 + so, Ap1 + ko);
            CP_ASYNC16(dB0 + so, Bp0 + ko);
            CP_ASYNC16(dB1 + so, Bp1 + ko);
        }
        CP_COMMIT();

        const uint32_t sA = sbase + (uint32_t)st * GSTAGE;
        const uint32_t sB = sA + 8192u;

#pragma unroll
        for (int ks = 0; ks < 2; ++ks) {
            uint32_t af[4][4];
            uint32_t bf[4][2];
#pragma unroll
            for (int mt = 0; mt < 4; ++mt) {
                const int mrow = a_mrow0 + mt * 16;
                const uint32_t addr = sA + swz16(mrow, ks * 2 + a_kq) * 16;
                ldsm_x4(af[mt][0], af[mt][1], af[mt][2], af[mt][3], addr);
            }
#pragma unroll
            for (int p = 0; p < 2; ++p) {
                const int nrow = b_nrow0 + p * 16;
                const uint32_t addr = sB + swz16(nrow, ks * 2 + b_kq) * 16;
                ldsm_x4(bf[p * 2][0], bf[p * 2][1], bf[p * 2 + 1][0], bf[p * 2 + 1][1], addr);
            }
#pragma unroll
            for (int mt = 0; mt < 4; ++mt)
#pragma unroll
                for (int nt = 0; nt < 4; ++nt)
                    mma_tf32(acc[mt][nt], af[mt], bf[nt]);
        }
        st = (st + 1) % 3;
    }

    // -------- epilogue --------
    const int r_base = m0 + warp_m * 64;
    const int c_base = n0 + warp_n * 32;
    const int rl = lane >> 2;
    const int cl = (lane & 3) * 2;

#pragma unroll
    for (int mt = 0; mt < 4; ++mt) {
#pragma unroll
        for (int half = 0; half < 2; ++half) {
            const int rr = r_base + mt * 16 + rl + half * 8;
            const int l = rr % SEQL;
            const int tt = l / NPATCH;
            const int pp = l % NPATCH;
#pragma unroll
            for (int nt = 0; nt < 4; ++nt) {
                const int col = c_base + nt * 8 + cl;
                float v0 = acc[mt][nt][half * 2 + 0] + bias[col];
                float v1 = acc[mt][nt][half * 2 + 1] + bias[col + 1];
                if (epi == EPI_EMBED) {
                    v0 += sp[(size_t)pp * DIM + col]     + tp[(size_t)tt * DIM + col];
                    v1 += sp[(size_t)pp * DIM + col + 1] + tp[(size_t)tt * DIM + col + 1];
                } else if (epi == EPI_RES) {
                    v0 += res[(size_t)rr * N + col];
                    v1 += res[(size_t)rr * N + col + 1];
                } else if (epi == EPI_GELU) {
                    v0 = 0.5f * v0 * (1.0f + erff(v0 * 0.70710678118654752f));
                    v1 = 0.5f * v1 * (1.0f + erff(v1 * 0.70710678118654752f));
                }
                *(float2*)(C + (size_t)rr * N + col) = make_float2(v0, v1);
            }
        }
    }
}

// ---------------- LayerNorm: one WARP per row of 512, shuffle-only ----------------
__global__ __launch_bounds__(256)
void ln_kernel(const float* __restrict__ x, const float* __restrict__ g,
               const float* __restrict__ b, float* __restrict__ y)
{
    const int row = blockIdx.x * 8 + (threadIdx.x >> 5);
    const int lane = threadIdx.x & 31;
    const float* xr = x + (size_t)row * DIM;

    float4 v[4];
#pragma unroll
    for (int w = 0; w < 4; ++w)
        v[w] = *(const float4*)(xr + w * 128 + lane * 4);

    float s = 0.f;
#pragma unroll
    for (int w = 0; w < 4; ++w) s += v[w].x + v[w].y + v[w].z + v[w].w;
#pragma unroll
    for (int o = 16; o > 0; o >>= 1) s += __shfl_xor_sync(0xffffffffu, s, o);
    const float mean = s * (1.0f / DIM);

    float q = 0.f;
#pragma unroll
    for (int w = 0; w < 4; ++w) {
        const float d0 = v[w].x - mean, d1 = v[w].y - mean;
        const float d2 = v[w].z - mean, d3 = v[w].w - mean;
        q += d0 * d0 + d1 * d1 + d2 * d2 + d3 * d3;
    }
#pragma unroll
    for (int o = 16; o > 0; o >>= 1) q += __shfl_xor_sync(0xffffffffu, q, o);
    const float rs = rsqrtf(q * (1.0f / DIM) + 1e-5f);

    float* yr = y + (size_t)row * DIM;
#pragma unroll
    for (int w = 0; w < 4; ++w) {
        const int col = w * 128 + lane * 4;
        const float4 gv = *(const float4*)(g + col);
        const float4 bv = *(const float4*)(b + col);
        float4 o4;
        o4.x = (v[w].x - mean) * rs * gv.x + bv.x;
        o4.y = (v[w].y - mean) * rs * gv.y + bv.y;
        o4.z = (v[w].z - mean) * rs * gv.z + bv.z;
        o4.w = (v[w].w - mean) * rs * gv.w + bv.w;
        *(float4*)(yr + col) = o4;
    }
}

// ---------------- flash attention over the kept suffix only ----------------
#define AT   64
#define APAD 68
__global__ __launch_bounds__(256)
void attn_kernel(const float* __restrict__ qkv, const int* __restrict__ s0arr,
                 float* __restrict__ out)
{
    const int qt = blockIdx.x;
    const int h  = blockIdx.y;
    const int n  = blockIdx.z;
    const int q0 = qt * AT;
    const int s0n = s0arr[n];
    if (q0 + AT <= s0n) return;

    extern __shared__ float sm[];
    float* Qt   = sm;
    float* Kt   = Qt + AT * APAD;
    float* Vs   = Kt + AT * APAD;
    float* Ps   = Vs + AT * APAD;
    float* mrow = Ps + AT * APAD;
    float* lrow = mrow + AT;
    float* crow = lrow + AT;

    const int tid = threadIdx.x;
    const int tx = tid & 15;
    const int ty = tid >> 4;
    const int tx4 = tx * 4, ty4 = ty * 4;

    const float* base = qkv + (size_t)n * SEQL * (3 * DIM);

#pragma unroll
    for (int it = 0; it < 4; ++it) {
        int idx = tid + it * 256;
        int row = idx >> 4;
        int cg  = (idx & 15) * 4;
        int qrow = q0 + row;
        int src = qrow < SEQL ? qrow : (SEQL - 1);
        float4 v = *(const float4*)(base + (size_t)src * (3 * DIM) + h * DH + cg);
        Qt[(cg + 0) * APAD + row] = v.x;
        Qt[(cg + 1) * APAD + row] = v.y;
        Qt[(cg + 2) * APAD + row] = v.z;
        Qt[(cg + 3) * APAD + row] = v.w;
    }
    if (tid < AT) {
        mrow[tid] = -1e30f;
        lrow[tid] = 0.f;
    }
    float o[4][4];
#pragma unroll
    for (int i = 0; i < 4; ++i)
#pragma unroll
        for (int j = 0; j < 4; ++j) o[i][j] = 0.f;
    __syncthreads();

    const int ktstart = (s0n / AT) * AT;

    for (int kt0 = ktstart; kt0 < SEQL; kt0 += AT) {
#pragma unroll
        for (int it = 0; it < 4; ++it) {
            int idx = tid + it * 256;
            int row = idx >> 4;
            int cg  = (idx & 15) * 4;
            int krow = kt0 + row;
            int src = krow < SEQL ? krow : (SEQL - 1);
            const float* kp = base + (size_t)src * (3 * DIM) + DIM + h * DH + cg;
            float4 k4 = *(const float4*)kp;
            Kt[(cg + 0) * APAD + row] = k4.x;
            Kt[(cg + 1) * APAD + row] = k4.y;
            Kt[(cg + 2) * APAD + row] = k4.z;
            Kt[(cg + 3) * APAD + row] = k4.w;
            const float* vp = base + (size_t)src * (3 * DIM) + 2 * DIM + h * DH + cg;
            float4 v4 = *(const float4*)vp;
            *(float4*)&Vs[row * APAD + cg] = v4;
        }
        __syncthreads();

        float s[4][4];
#pragma unroll
        for (int i = 0; i < 4; ++i)
#pragma unroll
            for (int j = 0; j < 4; ++j) s[i][j] = 0.f;
#pragma unroll 8
        for (int d = 0; d < DH; ++d) {
            float a[4], bb[4];
#pragma unroll
            for (int i = 0; i < 4; ++i) a[i] = Qt[d * APAD + ty4 + i];
#pragma unroll
            for (int j = 0; j < 4; ++j) bb[j] = Kt[d * APAD + tx4 + j];
#pragma unroll
            for (int i = 0; i < 4; ++i)
#pragma unroll
                for (int j = 0; j < 4; ++j)
                    s[i][j] = fmaf(a[i], bb[j], s[i][j]);
        }

#pragma unroll
        for (int i = 0; i < 4; ++i) {
#pragma unroll
            for (int j = 0; j < 4; ++j) {
                const int kidx = kt0 + tx4 + j;
                const float val = (kidx >= s0n && kidx < SEQL) ? s[i][j] * 0.125f : -1e30f;
                Ps[(ty4 + i) * APAD + tx4 + j] = val;
            }
        }
        __syncthreads();

        if (tid < AT) {
            float* pr = Ps + tid * APAD;
            float mo = mrow[tid];
            float tm = -1e30f;
#pragma unroll 8
            for (int k = 0; k < AT; ++k) tm = fmaxf(tm, pr[k]);
            float mn = fmaxf(mo, tm);
            float c = __expf(mo - mn);
            float srow = 0.f;
#pragma unroll 8
            for (int k = 0; k < AT; ++k) {
                float pv = pr[k];
                float e = (pv <= -1e29f) ? 0.f : __expf(pv - mn);
                pr[k] = e;
                srow += e;
            }
            lrow[tid] = lrow[tid] * c + srow;
            mrow[tid] = mn;
            crow[tid] = c;
        }
        __syncthreads();

        float ci[4];
#pragma unroll
        for (int i = 0; i < 4; ++i) ci[i] = crow[ty4 + i];
#pragma unroll
        for (int i = 0; i < 4; ++i)
#pragma unroll
            for (int j = 0; j < 4; ++j) o[i][j] *= ci[i];
#pragma unroll 8
        for (int k = 0; k < AT; ++k) {
            float p[4], vv[4];
#pragma unroll
            for (int i = 0; i < 4; ++i) p[i] = Ps[(ty4 + i) * APAD + k];
#pragma unroll
            for (int j = 0; j < 4; ++j) vv[j] = Vs[k * APAD + tx4 + j];
#pragma unroll
            for (int i = 0; i < 4; ++i)
#pragma unroll
                for (int j = 0; j < 4; ++j)
                    o[i][j] = fmaf(p[i], vv[j], o[i][j]);
        }
        __syncthreads();
    }

#pragma unroll
    for (int i = 0; i < 4; ++i) {
        const int q = q0 + ty4 + i;
        if (q < SEQL && q >= s0n) {
            const float inv = 1.0f / lrow[ty4 + i];
#pragma unroll
            for (int j = 0; j < 4; ++j)
                out[((size_t)n * SEQL + q) * DIM + h * DH + tx4 + j] = o[i][j] * inv;
        }
    }
}

#define ATT_SMEM ((4 * AT * APAD + 3 * AT) * (int)sizeof(float))

// ---------------- orchestration ----------------
extern "C" void kernel_launch(void* const* d_in, const int* in_sizes, int n_in,
                              void* d_out, int out_size)
{
    (void)in_sizes; (void)n_in; (void)out_size;
    const float* patch    = (const float*)d_in[0];
    const int*   done     = (const int*)  d_in[1];
    const float* W_embed  = (const float*)d_in[2];
    const float* b_embed  = (const float*)d_in[3];
    const float* spatial  = (const float*)d_in[4];
    const float* temporal = (const float*)d_in[5];
    const float* ln1_g    = (const float*)d_in[6];
    const float* ln1_b    = (const float*)d_in[7];
    const float* Wqkv     = (const float*)d_in[8];
    const float* bqkv     = (const float*)d_in[9];
    const float* Wo       = (const float*)d_in[10];
    const float* bo       = (const float*)d_in[11];
    const float* ln2_g    = (const float*)d_in[12];
    const float* ln2_b    = (const float*)d_in[13];
    const float* W1       = (const float*)d_in[14];
    const float* b1       = (const float*)d_in[15];
    const float* W2       = (const float*)d_in[16];
    const float* b2       = (const float*)d_in[17];
    const float* out_g    = (const float*)d_in[18];
    const float* out_b    = (const float*)d_in[19];
    float* out = (float*)d_out;

    float *x, *h, *qkv, *att, *mlp, *pm, *wT;
    int* s0;
    cudaGetSymbolAddress((void**)&x,    g_x);
    cudaGetSymbolAddress((void**)&h,    g_h);
    cudaGetSymbolAddress((void**)&qkv,  g_qkv);
    cudaGetSymbolAddress((void**)&att,  g_att);
    cudaGetSymbolAddress((void**)&mlp,  g_mlp);
    cudaGetSymbolAddress((void**)&pm,   g_pm);
    cudaGetSymbolAddress((void**)&s0,   g_s0);
    cudaGetSymbolAddress((void**)&wT,   g_wT);

    cudaFuncSetAttribute(attn_kernel, cudaFuncAttributeMaxDynamicSharedMemorySize, ATT_SMEM);
    cudaFuncSetAttribute(tgemm_kernel, cudaFuncAttributeMaxDynamicSharedMemorySize, TG_SMEM);

    float* qkvT = wT + OFF_QKVT;
    float* woT  = wT + OFF_WOT;
    float* w1T  = wT + OFF_W1T;
    float* w2T  = wT + OFF_W2T;
    float* webT = wT + OFF_WEBT;

    // weight transposes ([K][N] -> [N][K]), batched over layers via grid z
    dim3 tb(32, 8);
    transpose_kernel<<<dim3(16, 14, 1), tb>>>(W_embed, webT, PDIM, DIM);
    transpose_kernel<<<dim3(48, 16, DEPTH), tb>>>(Wqkv, qkvT, DIM, 3 * DIM);
    transpose_kernel<<<dim3(16, 16, DEPTH), tb>>>(Wo, woT, DIM, DIM);
    transpose_kernel<<<dim3(64, 16, DEPTH), tb>>>(W1, w1T, DIM, MLPD);
    transpose_kernel<<<dim3(16, 64, DEPTH), tb>>>(W2, w2T, MLPD, DIM);

    s0_kernel<<<1, 32>>>(done, s0);

    // patch embed + pos embed
    tgemm_kernel<<<dim3(DIM / 128, TOK / 128), 256, TG_SMEM>>>(
        patch, webT, b_embed, nullptr, x, TOK, DIM, PDIM, EPI_EMBED, spatial, temporal);

    for (int i = 0; i < DEPTH; ++i) {
        ln_kernel<<<TOK / 8, 256>>>(x, ln1_g + (size_t)i * DIM, ln1_b + (size_t)i * DIM, h);

        tgemm_kernel<<<dim3(3 * DIM / 128, TOK / 128), 256, TG_SMEM>>>(
            h, qkvT + (size_t)i * 3 * DIM * DIM, bqkv + (size_t)i * 3 * DIM,
            nullptr, qkv, TOK, 3 * DIM, DIM, EPI_NONE, nullptr, nullptr);

        pmean_kernel<<<dim3(8, NB), 512>>>(qkv, pm);
        fill_kernel<<<dim3(SEQL, NB), 512>>>(pm, s0, att);
        attn_kernel<<<dim3((SEQL + AT - 1) / AT, HEADS, NB), 256, ATT_SMEM>>>(qkv, s0, att);

        tgemm_kernel<<<dim3(DIM / 128, TOK / 128), 256, TG_SMEM>>>(
            att, woT + (size_t)i * DIM * DIM, bo + (size_t)i * DIM,
            x, x, TOK, DIM, DIM, EPI_RES, nullptr, nullptr);

        ln_kernel<<<TOK / 8, 256>>>(x, ln2_g + (size_t)i * DIM, ln2_b + (size_t)i * DIM, h);

        tgemm_kernel<<<dim3(MLPD / 128, TOK / 128), 256, TG_SMEM>>>(
            h, w1T + (size_t)i * DIM * MLPD, b1 + (size_t)i * MLPD,
            nullptr, mlp, TOK, MLPD, DIM, EPI_GELU, nullptr, nullptr);

        tgemm_kernel<<<dim3(DIM / 128, TOK / 128), 256, TG_SMEM>>>(
            mlp, w2T + (size_t)i * MLPD * DIM, b2 + (size_t)i * DIM,
            x, x, TOK, DIM, MLPD, EPI_RES, nullptr, nullptr);
    }

    ln_kernel<<<TOK / 8, 256>>>(x, out_g, out_b, out);
}

// round 7
// speedup vs baseline: 6.8033x; 1.3922x over previous
#include <cuda_runtime.h>
#include <cuda_fp16.h>
#include <cstdint>
#include <cstddef>

// ---------------- problem constants ----------------
#define NB      32
#define T_STEP  16
#define NPATCH  49
#define SEQL    784            // T_STEP * NUM_PATCHES
#define TOK     25088          // NB * SEQL
#define DIM     512
#define HEADS   8
#define DH      64
#define MLPD    2048
#define PDIM    432
#define PDIMP   448            // padded to a multiple of 32
#define DEPTH   4

// ---------------- scratch (device globals; no allocations allowed) ----------------
__device__ float  g_x  [(size_t)TOK * DIM];
__device__ float  g_qkv[(size_t)TOK * 3 * DIM];
__device__ int    g_s0 [NB];
__device__ float  g_pm [(size_t)NB * 8 * DIM];
__device__ __half g_h16  [(size_t)TOK * DIM];
__device__ __half g_att16[(size_t)TOK * DIM];
__device__ __half g_mlp16[(size_t)TOK * MLPD];
__device__ __half g_p16  [(size_t)TOK * PDIMP];

// transposed fp16 weights  [N][K] layouts (element offsets)
#define OFF_QKVT 0
#define OFF_WOT  3145728
#define OFF_W1T  4194304
#define OFF_W2T  8388608
#define OFF_WEBT 12582912
__device__ __half g_w16[12812288];

// ---------------- epilogue modes ----------------
#define EPI_NONE  0
#define EPI_EMBED 1
#define EPI_RES   2
#define EPI_GELU  3

// ---------------- helpers ----------------
__device__ __forceinline__ uint32_t smem_u32(const void* p) {
    uint32_t a;
    asm("{ .reg .u64 t; cvta.to.shared.u64 t, %1; cvt.u32.u64 %0, t; }" : "=r"(a) : "l"(p));
    return a;
}

__device__ __forceinline__ void mma_f16(float c[4], const uint32_t a[4], const uint32_t b[2]) {
    asm volatile(
        "mma.sync.aligned.m16n8k16.row.col.f32.f16.f16.f32 "
        "{%0,%1,%2,%3}, {%4,%5,%6,%7}, {%8,%9}, {%0,%1,%2,%3};\n"
        : "+f"(c[0]), "+f"(c[1]), "+f"(c[2]), "+f"(c[3])
        : "r"(a[0]), "r"(a[1]), "r"(a[2]), "r"(a[3]), "r"(b[0]), "r"(b[1]));
}

__device__ __forceinline__ void ldsm_x4(uint32_t& r0, uint32_t& r1, uint32_t& r2,
                                        uint32_t& r3, uint32_t addr) {
    asm volatile("ldmatrix.sync.aligned.m8n8.x4.shared.b16 {%0,%1,%2,%3}, [%4];"
                 : "=r"(r0), "=r"(r1), "=r"(r2), "=r"(r3) : "r"(addr));
}

#define CP_ASYNC16(dst, src) \
    asm volatile("cp.async.cg.shared.global [%0], [%1], 16;" :: "r"(dst), "l"(src))
#define CP_COMMIT() asm volatile("cp.async.commit_group;" ::: "memory")
#define CP_WAIT1()  asm volatile("cp.async.wait_group 1;" ::: "memory")

// swizzled 16B-unit offset in a 128-row x 64B-row operand tile
__device__ __forceinline__ uint32_t swz16(int m, int q) {
    return (uint32_t)(m * 4 + (q ^ ((m >> 1) & 3)));
}

// ---------------- episodic mask suffix start ----------------
__global__ void s0_kernel(const int* __restrict__ done, int* __restrict__ s0)
{
    int n = threadIdx.x;
    if (n >= NB) return;
    int last = -1;
    for (int t = 0; t < T_STEP - 1; ++t)
        if (done[n * (T_STEP - 1) + t]) last = t;
    s0[n] = (last + 1) * NPATCH;
}

// ---------------- partial V sums ----------------
__global__ void pmean_kernel(const float* __restrict__ qkv, float* __restrict__ pm)
{
    const int part = blockIdx.x;   // 0..7
    const int n = blockIdx.y;
    const int d = threadIdx.x;     // 512
    const float* base = qkv + (size_t)n * SEQL * (3 * DIM) + 2 * DIM + d;
    const int r0 = part * 98;
    float s = 0.f;
#pragma unroll 7
    for (int r = 0; r < 98; ++r)
        s += base[(size_t)(r0 + r) * (3 * DIM)];
    pm[((size_t)n * 8 + part) * DIM + d] = s;
}

// ---------------- fill masked-query rows with mean(V), fp16 out ----------------
__global__ void fill_kernel(const float* __restrict__ pm, const int* __restrict__ s0,
                            __half* __restrict__ out)
{
    const int q = blockIdx.x;
    const int n = blockIdx.y;
    if (q >= s0[n]) return;
    const int d = threadIdx.x;   // 512
    float s = 0.f;
#pragma unroll
    for (int p = 0; p < 8; ++p)
        s += pm[((size_t)n * 8 + p) * DIM + d];
    out[((size_t)n * SEQL + q) * DIM + d] = __float2half(s * (1.0f / 784.0f));
}

// ---------------- patch -> fp16 with zero pad to PDIMP ----------------
__global__ void cvt_patch_kernel(const float* __restrict__ p, __half* __restrict__ o)
{
    const int idx = blockIdx.x * 256 + threadIdx.x;        // TOK*PDIMP total
    const int tok = idx / PDIMP;
    const int c = idx % PDIMP;
    o[idx] = (c < PDIM) ? __float2half(p[(size_t)tok * PDIM + c]) : __half(0.f);
}

// ---------------- weight transpose: src[K][N] f32 -> dst[N][Kd] fp16 ----------
__global__ void transpose_kernel(const float* __restrict__ src0, __half* __restrict__ dst0,
                                 int K, int N, int Kd)
{
    const float* src = src0 + (size_t)blockIdx.z * K * N;
    __half* dst = dst0 + (size_t)blockIdx.z * N * Kd;
    __shared__ float t[32][33];
    int x = blockIdx.x * 32 + threadIdx.x;   // n
    int y = blockIdx.y * 32 + threadIdx.y;   // k
#pragma unroll
    for (int j = 0; j < 32; j += 8)
        if (x < N && y + j < K)
            t[threadIdx.y + j][threadIdx.x] = src[(size_t)(y + j) * N + x];
    __syncthreads();
    x = blockIdx.y * 32 + threadIdx.x;       // k
    y = blockIdx.x * 32 + threadIdx.y;       // n
#pragma unroll
    for (int j = 0; j < 32; j += 8)
        if (x < K && y + j < N)
            dst[(size_t)(y + j) * Kd + x] = __float2half(t[threadIdx.x][threadIdx.y + j]);
}

// ---------------- fp16 mma.sync GEMM, cp.async 3-stage pipeline ----------
// 128x128 CTA tile, BK=32 halves, 256 threads, warp grid 2(m) x 4(n), warp tile 64x32.
// smem: 3 stages x (A 8KB + B 8KB) = 48KB. fp32 accumulate. Requires K%32==0.
#define GSTAGE 16384u
#define TG_SMEM (3 * 16384)
__global__ __launch_bounds__(256, 2)
void tgemm_kernel(const __half* __restrict__ A, const __half* __restrict__ Bt,
                  const float* __restrict__ bias, const float* __restrict__ res,
                  float* __restrict__ Cf, __half* __restrict__ Ch,
                  int M, int N, int K, int epi,
                  const float* __restrict__ sp, const float* __restrict__ tp)
{
    extern __shared__ __align__(16) uint8_t smraw[];

    const int tid = threadIdx.x;
    const int lane = tid & 31;
    const int wid = tid >> 5;
    const int warp_m = wid >> 2;
    const int warp_n = wid & 3;
    const int n0 = blockIdx.x * 128;
    const int m0 = blockIdx.y * 128;

    // loaders: row = tid>>1 (0..127), units l_u, l_u+1 (16B = 8 halves each)
    const int l_m = tid >> 1;
    const int l_u = (tid & 1) * 2;

    const uint32_t sbase = smem_u32(smraw);
    const uint32_t dA0 = sbase + swz16(l_m, l_u) * 16;
    const uint32_t dA1 = sbase + swz16(l_m, l_u + 1) * 16;
    const uint32_t dB0 = dA0 + 8192u;
    const uint32_t dB1 = dA1 + 8192u;

    const __half* Ap = A + (size_t)(m0 + l_m) * K + l_u * 8;
    const __half* Bp = Bt + (size_t)(n0 + l_m) * K + l_u * 8;

    const int g = lane >> 3;
    const int r = lane & 7;
    const int a_mrow0 = warp_m * 64 + (g & 1) * 8 + r;
    const int a_kq = g >> 1;                 // unit within k-step
    const int b_nrow0 = warp_n * 32 + (g >> 1) * 8 + r;
    const int b_kq = g & 1;

    float acc[4][4][4];
#pragma unroll
    for (int mt = 0; mt < 4; ++mt)
#pragma unroll
        for (int nt = 0; nt < 4; ++nt)
#pragma unroll
            for (int e = 0; e < 4; ++e) acc[mt][nt][e] = 0.f;

    const int niter = K >> 5;                // BK = 32 halves

    // prologue: stages 0 and 1
    CP_ASYNC16(dA0, Ap);
    CP_ASYNC16(dA1, Ap + 8);
    CP_ASYNC16(dB0, Bp);
    CP_ASYNC16(dB1, Bp + 8);
    CP_COMMIT();
    CP_ASYNC16(dA0 + GSTAGE, Ap + 32);
    CP_ASYNC16(dA1 + GSTAGE, Ap + 40);
    CP_ASYNC16(dB0 + GSTAGE, Bp + 32);
    CP_ASYNC16(dB1 + GSTAGE, Bp + 40);
    CP_COMMIT();

    int st = 0;
    for (int i = 0; i < niter; ++i) {
        CP_WAIT1();
        __syncthreads();

        if (i + 2 < niter) {
            const int ko = (i + 2) * 32;
            const uint32_t so = (uint32_t)((st + 2) % 3) * GSTAGE;
            CP_ASYNC16(dA0 + so, Ap + ko);
            CP_ASYNC16(dA1 + so, Ap + ko + 8);
            CP_ASYNC16(dB0 + so, Bp + ko);
            CP_ASYNC16(dB1 + so, Bp + ko + 8);
        }
        CP_COMMIT();

        const uint32_t sA = sbase + (uint32_t)st * GSTAGE;
        const uint32_t sB = sA + 8192u;

#pragma unroll
        for (int ks = 0; ks < 2; ++ks) {        // two k16 steps per BK=32
            uint32_t af[4][4];
            uint32_t bf[4][2];
#pragma unroll
            for (int mt = 0; mt < 4; ++mt) {
                const int mrow = a_mrow0 + mt * 16;
                const uint32_t addr = sA + swz16(mrow, ks * 2 + a_kq) * 16;
                ldsm_x4(af[mt][0], af[mt][1], af[mt][2], af[mt][3], addr);
            }
#pragma unroll
            for (int p = 0; p < 2; ++p) {
                const int nrow = b_nrow0 + p * 16;
                const uint32_t addr = sB + swz16(nrow, ks * 2 + b_kq) * 16;
                ldsm_x4(bf[p * 2][0], bf[p * 2][1], bf[p * 2 + 1][0], bf[p * 2 + 1][1], addr);
            }
#pragma unroll
            for (int mt = 0; mt < 4; ++mt)
#pragma unroll
                for (int nt = 0; nt < 4; ++nt)
                    mma_f16(acc[mt][nt], af[mt], bf[nt]);
        }
        st = (st + 1) % 3;
    }

    // -------- epilogue --------
    const int r_base = m0 + warp_m * 64;
    const int c_base = n0 + warp_n * 32;
    const int rl = lane >> 2;
    const int cl = (lane & 3) * 2;

#pragma unroll
    for (int mt = 0; mt < 4; ++mt) {
#pragma unroll
        for (int half = 0; half < 2; ++half) {
            const int rr = r_base + mt * 16 + rl + half * 8;
            const int l = rr % SEQL;
            const int tt = l / NPATCH;
            const int pp = l % NPATCH;
#pragma unroll
            for (int nt = 0; nt < 4; ++nt) {
                const int col = c_base + nt * 8 + cl;
                float v0 = acc[mt][nt][half * 2 + 0] + bias[col];
                float v1 = acc[mt][nt][half * 2 + 1] + bias[col + 1];
                if (epi == EPI_EMBED) {
                    v0 += sp[(size_t)pp * DIM + col]     + tp[(size_t)tt * DIM + col];
                    v1 += sp[(size_t)pp * DIM + col + 1] + tp[(size_t)tt * DIM + col + 1];
                } else if (epi == EPI_RES) {
                    v0 += res[(size_t)rr * N + col];
                    v1 += res[(size_t)rr * N + col + 1];
                } else if (epi == EPI_GELU) {
                    v0 = 0.5f * v0 * (1.0f + erff(v0 * 0.70710678118654752f));
                    v1 = 0.5f * v1 * (1.0f + erff(v1 * 0.70710678118654752f));
                    *(__half2*)(Ch + (size_t)rr * N + col) = __floats2half2_rn(v0, v1);
                    continue;
                }
                *(float2*)(Cf + (size_t)rr * N + col) = make_float2(v0, v1);
            }
        }
    }
}

// ---------------- LayerNorm: one WARP per row of 512, templated output ----------------
template <bool HOUT>
__global__ __launch_bounds__(256)
void ln_kernel(const float* __restrict__ x, const float* __restrict__ g,
               const float* __restrict__ b, float* __restrict__ yf,
               __half* __restrict__ yh)
{
    const int row = blockIdx.x * 8 + (threadIdx.x >> 5);
    const int lane = threadIdx.x & 31;
    const float* xr = x + (size_t)row * DIM;

    float4 v[4];
#pragma unroll
    for (int w = 0; w < 4; ++w)
        v[w] = *(const float4*)(xr + w * 128 + lane * 4);

    float s = 0.f;
#pragma unroll
    for (int w = 0; w < 4; ++w) s += v[w].x + v[w].y + v[w].z + v[w].w;
#pragma unroll
    for (int o = 16; o > 0; o >>= 1) s += __shfl_xor_sync(0xffffffffu, s, o);
    const float mean = s * (1.0f / DIM);

    float q = 0.f;
#pragma unroll
    for (int w = 0; w < 4; ++w) {
        const float d0 = v[w].x - mean, d1 = v[w].y - mean;
        const float d2 = v[w].z - mean, d3 = v[w].w - mean;
        q += d0 * d0 + d1 * d1 + d2 * d2 + d3 * d3;
    }
#pragma unroll
    for (int o = 16; o > 0; o >>= 1) q += __shfl_xor_sync(0xffffffffu, q, o);
    const float rs = rsqrtf(q * (1.0f / DIM) + 1e-5f);

#pragma unroll
    for (int w = 0; w < 4; ++w) {
        const int col = w * 128 + lane * 4;
        const float4 gv = *(const float4*)(g + col);
        const float4 bv = *(const float4*)(b + col);
        float4 o4;
        o4.x = (v[w].x - mean) * rs * gv.x + bv.x;
        o4.y = (v[w].y - mean) * rs * gv.y + bv.y;
        o4.z = (v[w].z - mean) * rs * gv.z + bv.z;
        o4.w = (v[w].w - mean) * rs * gv.w + bv.w;
        if (HOUT) {
            __half2 h0 = __floats2half2_rn(o4.x, o4.y);
            __half2 h1 = __floats2half2_rn(o4.z, o4.w);
            uint2 pk;
            pk.x = *(uint32_t*)&h0;
            pk.y = *(uint32_t*)&h1;
            *(uint2*)(yh + (size_t)row * DIM + col) = pk;
        } else {
            *(float4*)(yf + (size_t)row * DIM + col) = o4;
        }
    }
}

// ---------------- flash attention over the kept suffix only, fp16 out ----------------
#define AT   64
#define APAD 68
__global__ __launch_bounds__(256)
void attn_kernel(const float* __restrict__ qkv, const int* __restrict__ s0arr,
                 __half* __restrict__ out)
{
    const int qt = blockIdx.x;
    const int h  = blockIdx.y;
    const int n  = blockIdx.z;
    const int q0 = qt * AT;
    const int s0n = s0arr[n];
    if (q0 + AT <= s0n) return;

    extern __shared__ float sm[];
    float* Qt   = sm;
    float* Kt   = Qt + AT * APAD;
    float* Vs   = Kt + AT * APAD;
    float* Ps   = Vs + AT * APAD;
    float* mrow = Ps + AT * APAD;
    float* lrow = mrow + AT;
    float* crow = lrow + AT;

    const int tid = threadIdx.x;
    const int tx = tid & 15;
    const int ty = tid >> 4;
    const int tx4 = tx * 4, ty4 = ty * 4;

    const float* base = qkv + (size_t)n * SEQL * (3 * DIM);

#pragma unroll
    for (int it = 0; it < 4; ++it) {
        int idx = tid + it * 256;
        int row = idx >> 4;
        int cg  = (idx & 15) * 4;
        int qrow = q0 + row;
        int src = qrow < SEQL ? qrow : (SEQL - 1);
        float4 v = *(const float4*)(base + (size_t)src * (3 * DIM) + h * DH + cg);
        Qt[(cg + 0) * APAD + row] = v.x;
        Qt[(cg + 1) * APAD + row] = v.y;
        Qt[(cg + 2) * APAD + row] = v.z;
        Qt[(cg + 3) * APAD + row] = v.w;
    }
    if (tid < AT) {
        mrow[tid] = -1e30f;
        lrow[tid] = 0.f;
    }
    float o[4][4];
#pragma unroll
    for (int i = 0; i < 4; ++i)
#pragma unroll
        for (int j = 0; j < 4; ++j) o[i][j] = 0.f;
    __syncthreads();

    const int ktstart = (s0n / AT) * AT;

    for (int kt0 = ktstart; kt0 < SEQL; kt0 += AT) {
#pragma unroll
        for (int it = 0; it < 4; ++it) {
            int idx = tid + it * 256;
            int row = idx >> 4;
            int cg  = (idx & 15) * 4;
            int krow = kt0 + row;
            int src = krow < SEQL ? krow : (SEQL - 1);
            const float* kp = base + (size_t)src * (3 * DIM) + DIM + h * DH + cg;
            float4 k4 = *(const float4*)kp;
            Kt[(cg + 0) * APAD + row] = k4.x;
            Kt[(cg + 1) * APAD + row] = k4.y;
            Kt[(cg + 2) * APAD + row] = k4.z;
            Kt[(cg + 3) * APAD + row] = k4.w;
            const float* vp = base + (size_t)src * (3 * DIM) + 2 * DIM + h * DH + cg;
            float4 v4 = *(const float4*)vp;
            *(float4*)&Vs[row * APAD + cg] = v4;
        }
        __syncthreads();

        float s[4][4];
#pragma unroll
        for (int i = 0; i < 4; ++i)
#pragma unroll
            for (int j = 0; j < 4; ++j) s[i][j] = 0.f;
#pragma unroll 8
        for (int d = 0; d < DH; ++d) {
            float a[4], bb[4];
#pragma unroll
            for (int i = 0; i < 4; ++i) a[i] = Qt[d * APAD + ty4 + i];
#pragma unroll
            for (int j = 0; j < 4; ++j) bb[j] = Kt[d * APAD + tx4 + j];
#pragma unroll
            for (int i = 0; i < 4; ++i)
#pragma unroll
                for (int j = 0; j < 4; ++j)
                    s[i][j] = fmaf(a[i], bb[j], s[i][j]);
        }

#pragma unroll
        for (int i = 0; i < 4; ++i) {
#pragma unroll
            for (int j = 0; j < 4; ++j) {
                const int kidx = kt0 + tx4 + j;
                const float val = (kidx >= s0n && kidx < SEQL) ? s[i][j] * 0.125f : -1e30f;
                Ps[(ty4 + i) * APAD + tx4 + j] = val;
            }
        }
        __syncthreads();

        if (tid < AT) {
            float* pr = Ps + tid * APAD;
            float mo = mrow[tid];
            float tm = -1e30f;
#pragma unroll 8
            for (int k = 0; k < AT; ++k) tm = fmaxf(tm, pr[k]);
            float mn = fmaxf(mo, tm);
            float c = __expf(mo - mn);
            float srow = 0.f;
#pragma unroll 8
            for (int k = 0; k < AT; ++k) {
                float pv = pr[k];
                float e = (pv <= -1e29f) ? 0.f : __expf(pv - mn);
                pr[k] = e;
                srow += e;
            }
            lrow[tid] = lrow[tid] * c + srow;
            mrow[tid] = mn;
            crow[tid] = c;
        }
        __syncthreads();

        float ci[4];
#pragma unroll
        for (int i = 0; i < 4; ++i) ci[i] = crow[ty4 + i];
#pragma unroll
        for (int i = 0; i < 4; ++i)
#pragma unroll
            for (int j = 0; j < 4; ++j) o[i][j] *= ci[i];
#pragma unroll 8
        for (int k = 0; k < AT; ++k) {
            float p[4], vv[4];
#pragma unroll
            for (int i = 0; i < 4; ++i) p[i] = Ps[(ty4 + i) * APAD + k];
#pragma unroll
            for (int j = 0; j < 4; ++j) vv[j] = Vs[k * APAD + tx4 + j];
#pragma unroll
            for (int i = 0; i < 4; ++i)
#pragma unroll
                for (int j = 0; j < 4; ++j)
                    o[i][j] = fmaf(p[i], vv[j], o[i][j]);
        }
        __syncthreads();
    }

#pragma unroll
    for (int i = 0; i < 4; ++i) {
        const int q = q0 + ty4 + i;
        if (q < SEQL && q >= s0n) {
            const float inv = 1.0f / lrow[ty4 + i];
            __half* op = out + ((size_t)n * SEQL + q) * DIM + h * DH + tx4;
            *(__half2*)(op)     = __floats2half2_rn(o[i][0] * inv, o[i][1] * inv);
            *(__half2*)(op + 2) = __floats2half2_rn(o[i][2] * inv, o[i][3] * inv);
        }
    }
}

#define ATT_SMEM ((4 * AT * APAD + 3 * AT) * (int)sizeof(float))

// ---------------- orchestration ----------------
extern "C" void kernel_launch(void* const* d_in, const int* in_sizes, int n_in,
                              void* d_out, int out_size)
{
    (void)in_sizes; (void)n_in; (void)out_size;
    const float* patch    = (const float*)d_in[0];
    const int*   done     = (const int*)  d_in[1];
    const float* W_embed  = (const float*)d_in[2];
    const float* b_embed  = (const float*)d_in[3];
    const float* spatial  = (const float*)d_in[4];
    const float* temporal = (const float*)d_in[5];
    const float* ln1_g    = (const float*)d_in[6];
    const float* ln1_b    = (const float*)d_in[7];
    const float* Wqkv     = (const float*)d_in[8];
    const float* bqkv     = (const float*)d_in[9];
    const float* Wo       = (const float*)d_in[10];
    const float* bo       = (const float*)d_in[11];
    const float* ln2_g    = (const float*)d_in[12];
    const float* ln2_b    = (const float*)d_in[13];
    const float* W1       = (const float*)d_in[14];
    const float* b1       = (const float*)d_in[15];
    const float* W2       = (const float*)d_in[16];
    const float* b2       = (const float*)d_in[17];
    const float* out_g    = (const float*)d_in[18];
    const float* out_b    = (const float*)d_in[19];
    float* out = (float*)d_out;

    float *x, *qkv, *pm;
    __half *h16, *att16, *mlp16, *p16, *w16;
    int* s0;
    cudaGetSymbolAddress((void**)&x,     g_x);
    cudaGetSymbolAddress((void**)&qkv,   g_qkv);
    cudaGetSymbolAddress((void**)&pm,    g_pm);
    cudaGetSymbolAddress((void**)&s0,    g_s0);
    cudaGetSymbolAddress((void**)&h16,   g_h16);
    cudaGetSymbolAddress((void**)&att16, g_att16);
    cudaGetSymbolAddress((void**)&mlp16, g_mlp16);
    cudaGetSymbolAddress((void**)&p16,   g_p16);
    cudaGetSymbolAddress((void**)&w16,   g_w16);

    cudaFuncSetAttribute(attn_kernel, cudaFuncAttributeMaxDynamicSharedMemorySize, ATT_SMEM);
    cudaFuncSetAttribute(tgemm_kernel, cudaFuncAttributeMaxDynamicSharedMemorySize, TG_SMEM);

    __half* qkvT = w16 + OFF_QKVT;
    __half* woT  = w16 + OFF_WOT;
    __half* w1T  = w16 + OFF_W1T;
    __half* w2T  = w16 + OFF_W2T;
    __half* webT = w16 + OFF_WEBT;

    // weight transposes ([K][N] f32 -> [N][Kd] fp16), batched over layers
    dim3 tb(32, 8);
    transpose_kernel<<<dim3(16, 14, 1), tb>>>(W_embed, webT, PDIM, DIM, PDIMP);
    transpose_kernel<<<dim3(48, 16, DEPTH), tb>>>(Wqkv, qkvT, DIM, 3 * DIM, DIM);
    transpose_kernel<<<dim3(16, 16, DEPTH), tb>>>(Wo, woT, DIM, DIM, DIM);
    transpose_kernel<<<dim3(64, 16, DEPTH), tb>>>(W1, w1T, DIM, MLPD, DIM);
    transpose_kernel<<<dim3(16, 64, DEPTH), tb>>>(W2, w2T, MLPD, DIM, MLPD);

    s0_kernel<<<1, 32>>>(done, s0);
    cvt_patch_kernel<<<(TOK * PDIMP) / 256, 256>>>(patch, p16);

    // patch embed + pos embed  (A fp16 padded to 448)
    tgemm_kernel<<<dim3(DIM / 128, TOK / 128), 256, TG_SMEM>>>(
        p16, webT, b_embed, nullptr, x, nullptr, TOK, DIM, PDIMP, EPI_EMBED,
        spatial, temporal);

    for (int i = 0; i < DEPTH; ++i) {
        ln_kernel<true><<<TOK / 8, 256>>>(x, ln1_g + (size_t)i * DIM,
                                          ln1_b + (size_t)i * DIM, nullptr, h16);

        tgemm_kernel<<<dim3(3 * DIM / 128, TOK / 128), 256, TG_SMEM>>>(
            h16, qkvT + (size_t)i * 3 * DIM * DIM, bqkv + (size_t)i * 3 * DIM,
            nullptr, qkv, nullptr, TOK, 3 * DIM, DIM, EPI_NONE, nullptr, nullptr);

        pmean_kernel<<<dim3(8, NB), 512>>>(qkv, pm);
        fill_kernel<<<dim3(SEQL, NB), 512>>>(pm, s0, att16);
        attn_kernel<<<dim3((SEQL + AT - 1) / AT, HEADS, NB), 256, ATT_SMEM>>>(qkv, s0, att16);

        tgemm_kernel<<<dim3(DIM / 128, TOK / 128), 256, TG_SMEM>>>(
            att16, woT + (size_t)i * DIM * DIM, bo + (size_t)i * DIM,
            x, x, nullptr, TOK, DIM, DIM, EPI_RES, nullptr, nullptr);

        ln_kernel<true><<<TOK / 8, 256>>>(x, ln2_g + (size_t)i * DIM,
                                          ln2_b + (size_t)i * DIM, nullptr, h16);

        tgemm_kernel<<<dim3(MLPD / 128, TOK / 128), 256, TG_SMEM>>>(
            h16, w1T + (size_t)i * DIM * MLPD, b1 + (size_t)i * MLPD,
            nullptr, nullptr, mlp16, TOK, MLPD, DIM, EPI_GELU, nullptr, nullptr);

        tgemm_kernel<<<dim3(DIM / 128, TOK / 128), 256, TG_SMEM>>>(
            mlp16, w2T + (size_t)i * MLPD * DIM, b2 + (size_t)i * DIM,
            x, x, nullptr, TOK, DIM, MLPD, EPI_RES, nullptr, nullptr);
    }

    ln_kernel<false><<<TOK / 8, 256>>>(x, out_g, out_b, out, nullptr);
}